// round 9
// baseline (speedup 1.0000x reference)
#include <cuda_runtime.h>
#include <cuda_fp16.h>
#include <cuda_bf16.h>
#include <math.h>
#include <stdint.h>

// Problem constants (fixed by the dataset)
#define NN 8192
#define EE 65536
#define F_IN 512
#define H1D 4096
#define H2D 1024
#define F_OUT 10

// ---------------- scratch (device globals: allocation-free) ----------------
__device__ int    g_is64;
__device__ float  g_deg[NN];
__device__ float  g_dinv[NN];
__device__ int    g_src[EE];
__device__ int    g_dst[EE];
__device__ float  g_norm[EE];
__device__ int    g_rowstart[NN + 1];
__device__ int    g_cursor[NN];
__device__ int    g_csrc[EE];
__device__ float  g_cnorm[EE];
__device__ __half g_aggxh[(size_t)NN * F_IN];    // fp16 aggregated x
__device__ __half g_w1t[(size_t)H1D * F_IN];     // W1^T fp16 [4096][512]
__device__ __half g_w2t[(size_t)H2D * H1D];      // W2^T fp16 [1024][4096]
__device__ __half g_h1h[(size_t)NN * H1D];       // layer1 out fp16
__device__ __half g_t2h[(size_t)NN * H2D];       // h1 @ W2 fp16
__device__ __half g_h2h[(size_t)NN * H2D];       // relu(A t2 + b2) fp16
__device__ float  g_t3[(size_t)NN * F_OUT];
__device__ float  g_a3[(size_t)NN * F_OUT];

// ---------------- graph preprocessing ----------------
__device__ __forceinline__ int edge_val(const void* ei, int idx) {
    if (g_is64) return (int)((const long long*)ei)[idx];
    return ((const int*)ei)[idx];
}

// deg init + dtype probe in one kernel (probe in block 0, thread 0)
__global__ void k_deg_init(const void* __restrict__ ei) {
    int i = blockIdx.x * blockDim.x + threadIdx.x;
    if (i < NN) g_deg[i] = 1.0f;
    if (i == 0) {
        const long long* p = (const long long*)ei;
        int ok64 = 1;
        for (int j = 0; j < 64; j++) {
            long long v = p[j];
            if (v < 0 || v >= NN) { ok64 = 0; break; }
        }
        g_is64 = ok64;
    }
}

__global__ void k_deg_count(const void* __restrict__ ei) {
    int e = blockIdx.x * blockDim.x + threadIdx.x;
    if (e < EE) atomicAdd(&g_deg[edge_val(ei, EE + e)], 1.0f);
}

__global__ void k_dinv() {
    int i = blockIdx.x * blockDim.x + threadIdx.x;
    if (i < NN) g_dinv[i] = rsqrtf(g_deg[i]);
}

__global__ void k_edge_prep(const void* __restrict__ ei) {
    int e = blockIdx.x * blockDim.x + threadIdx.x;
    if (e < EE) {
        int s = edge_val(ei, e);
        int d = edge_val(ei, EE + e);
        g_src[e] = s;
        g_dst[e] = d;
        g_norm[e] = g_dinv[s] * g_dinv[d];
    }
}

// exclusive scan of (deg-1) over NN nodes; 1 block, 256 threads, 32 nodes each
__global__ void k_scan() {
    __shared__ int part[256];
    int t = threadIdx.x;
    int base = t * 32;
    int cnt[32];
    int s = 0;
#pragma unroll
    for (int i = 0; i < 32; i++) {
        cnt[i] = (int)g_deg[base + i] - 1;
        s += cnt[i];
    }
    part[t] = s;
    __syncthreads();
    for (int off = 1; off < 256; off <<= 1) {
        int v = (t >= off) ? part[t - off] : 0;
        __syncthreads();
        part[t] += v;
        __syncthreads();
    }
    int run = (t > 0) ? part[t - 1] : 0;
#pragma unroll
    for (int i = 0; i < 32; i++) {
        g_rowstart[base + i] = run;
        g_cursor[base + i] = 0;
        run += cnt[i];
    }
    if (t == 255) g_rowstart[NN] = run;
}

__global__ void k_place() {
    int e = blockIdx.x * blockDim.x + threadIdx.x;
    if (e >= EE) return;
    int d = g_dst[e];
    int pos = g_rowstart[d] + atomicAdd(&g_cursor[d], 1);
    g_csrc[pos]  = g_src[e];
    g_cnorm[pos] = g_norm[e];
}

// ---------------- CSR gather aggregation ----------------
// layer 1: out[r,:] = dinv^2 * x[r,:] + sum norm * x[src,:]   -> fp16 out
__global__ void k_gather1(const float* __restrict__ x, __half* __restrict__ out) {
    const int r = blockIdx.x;
    const int f = threadIdx.x;             // 0..127 (float4 lanes, F=512)
    const int s0 = g_rowstart[r], s1 = g_rowstart[r + 1];
    float di = g_dinv[r];
    float self = di * di;
    float4 v = ((const float4*)x)[(size_t)r * 128 + f];
    float4 acc = make_float4(v.x * self, v.y * self, v.z * self, v.w * self);
    for (int i = s0; i < s1; i++) {
        int src = g_csrc[i];
        float nrm = g_cnorm[i];
        float4 u = ((const float4*)x)[(size_t)src * 128 + f];
        acc.x += nrm * u.x; acc.y += nrm * u.y;
        acc.z += nrm * u.z; acc.w += nrm * u.w;
    }
    __half2 h0 = __floats2half2_rn(acc.x, acc.y);
    __half2 h1 = __floats2half2_rn(acc.z, acc.w);
    uint2 p;
    p.x = *(uint32_t*)&h0;
    p.y = *(uint32_t*)&h1;
    ((uint2*)out)[(size_t)r * 128 + f] = p;
}

// layer 2 (fp16 in/out): out[r,:] = relu( dinv^2*t2[r,:] + sum norm*t2[src,:] + bias )
__global__ void k_gather2h(const __half* __restrict__ t2, const float* __restrict__ bias,
                           __half* __restrict__ out) {
    const int r = blockIdx.x;
    const int f = threadIdx.x;             // 0..255 (4-half lanes, F=1024)
    const int s0 = g_rowstart[r], s1 = g_rowstart[r + 1];
    float di = g_dinv[r];
    float self = di * di;
    uint2 v = ((const uint2*)t2)[(size_t)r * 256 + f];
    float2 f0 = __half22float2(*(__half2*)&v.x);
    float2 f1 = __half22float2(*(__half2*)&v.y);
    float4 acc = make_float4(f0.x * self, f0.y * self, f1.x * self, f1.y * self);
    for (int i = s0; i < s1; i++) {
        int src = g_csrc[i];
        float nrm = g_cnorm[i];
        uint2 u = ((const uint2*)t2)[(size_t)src * 256 + f];
        float2 u0 = __half22float2(*(__half2*)&u.x);
        float2 u1 = __half22float2(*(__half2*)&u.y);
        acc.x += nrm * u0.x; acc.y += nrm * u0.y;
        acc.z += nrm * u1.x; acc.w += nrm * u1.y;
    }
    float4 b = ((const float4*)bias)[f];
    acc.x = fmaxf(acc.x + b.x, 0.0f);
    acc.y = fmaxf(acc.y + b.y, 0.0f);
    acc.z = fmaxf(acc.z + b.z, 0.0f);
    acc.w = fmaxf(acc.w + b.w, 0.0f);
    __half2 o0 = __floats2half2_rn(acc.x, acc.y);
    __half2 o1 = __floats2half2_rn(acc.z, acc.w);
    uint2 p;
    p.x = *(uint32_t*)&o0;
    p.y = *(uint32_t*)&o1;
    ((uint2*)out)[(size_t)r * 256 + f] = p;
}

// layer 3: scalar gather at F=10
__global__ void k_gather3(const float* __restrict__ t3, float* __restrict__ out) {
    int idx = blockIdx.x * blockDim.x + threadIdx.x;
    if (idx >= NN * F_OUT) return;
    int r = idx / F_OUT;
    int f = idx - r * F_OUT;
    const int s0 = g_rowstart[r], s1 = g_rowstart[r + 1];
    float di = g_dinv[r];
    float acc = di * di * t3[(size_t)r * F_OUT + f];
    for (int i = s0; i < s1; i++)
        acc += g_cnorm[i] * t3[(size_t)g_csrc[i] * F_OUT + f];
    out[idx] = acc;
}

// ---------------- transpose + convert: in[R][C] fp32 -> out[C][R] fp16 ----------------
__global__ void k_transpose_h(const float* __restrict__ in, __half* __restrict__ out,
                              int R, int C) {
    __shared__ float t[32][33];
    int c0 = blockIdx.x * 32, r0 = blockIdx.y * 32;
#pragma unroll
    for (int i = threadIdx.y; i < 32; i += 8)
        t[i][threadIdx.x] = in[(size_t)(r0 + i) * C + c0 + threadIdx.x];
    __syncthreads();
#pragma unroll
    for (int i = threadIdx.y; i < 32; i += 8)
        out[(size_t)(c0 + i) * R + r0 + threadIdx.x] = __float2half(t[threadIdx.x][i]);
}

// ---------------- FP16 tensor-core GEMM, cp.async 3-stage pipeline ----------------
// C[M,N] = A[M,K] @ B[N,K]^T : A, B fp16 k-contiguous.
// Block 128(M) x 256(N), K-chunk 32, 256 threads = 8 warps (2M x 4N), warp 64x64.

#define HLD 40                           // halves per smem row (32 + 8 pad)
#define A_ST (128 * HLD)                 // A halves per stage (5120)
#define B_ST (256 * HLD)                 // B halves per stage (10240)
#define NSTAGE 3
#define GEMM_SMEM (NSTAGE * (A_ST + B_ST) * 2)   // 92160 bytes

__device__ __forceinline__ uint32_t smem_u32(const void* p) {
    uint32_t a;
    asm("{ .reg .u64 t; cvta.to.shared.u64 t, %1; cvt.u32.u64 %0, t; }" : "=r"(a) : "l"(p));
    return a;
}

__device__ __forceinline__ void mma_f16(float c[4], uint32_t a0, uint32_t a1,
                                        uint32_t a2, uint32_t a3,
                                        uint32_t b0, uint32_t b1) {
    asm volatile(
        "mma.sync.aligned.m16n8k16.row.col.f32.f16.f16.f32 "
        "{%0,%1,%2,%3}, {%4,%5,%6,%7}, {%8,%9}, {%0,%1,%2,%3};"
        : "+f"(c[0]), "+f"(c[1]), "+f"(c[2]), "+f"(c[3])
        : "r"(a0), "r"(a1), "r"(a2), "r"(a3), "r"(b0), "r"(b1));
}

template<bool BIAS_RELU, bool OUT_HALF>
__global__ __launch_bounds__(256, 1)
void hgemm(const __half* __restrict__ A, const __half* __restrict__ B,
           const float* __restrict__ bias, void* __restrict__ Cv,
           int M, int N, int K) {
    extern __shared__ __half smh[];
    const uint32_t sb = smem_u32(smh);

    const int tid  = threadIdx.x;
    const int lane = tid & 31;
    const int w    = tid >> 5;
    const int wm   = w >> 2;              // 0..1  (64-row slab)
    const int wn   = w & 3;               // 0..3  (64-col slab)
    const int bm   = blockIdx.y * 128;
    const int bn   = blockIdx.x * 256;

    // cp.async mapping: A 512 16B-chunks, B 1024 16B-chunks; thread does 2 + 4
    const int r0 = tid >> 2;              // 0..63
    const int kc = tid & 3;               // 8-half group

    float acc[4][8][4];
#pragma unroll
    for (int i = 0; i < 4; i++)
#pragma unroll
        for (int j = 0; j < 8; j++)
#pragma unroll
            for (int r = 0; r < 4; r++) acc[i][j][r] = 0.0f;

    const int nch = K >> 5;

    auto issue = [&](int chunk, int s) {
        const __half* Ag = A + (size_t)bm * K + chunk * 32;
        const __half* Bg = B + (size_t)bn * K + chunk * 32;
        const uint32_t Ab = sb + s * (A_ST * 2);
        const uint32_t Bb = sb + (NSTAGE * A_ST + s * B_ST) * 2;
        const uint32_t so0 = (uint32_t)(r0 * HLD + kc * 8) * 2;
#pragma unroll
        for (int j = 0; j < 2; j++) {
            const int row = r0 + j * 64;
            const __half* ga = Ag + (size_t)row * K + kc * 8;
            asm volatile("cp.async.cg.shared.global [%0], [%1], 16;"
                         :: "r"(Ab + so0 + (uint32_t)(j * 64 * HLD * 2)), "l"(ga));
        }
#pragma unroll
        for (int j = 0; j < 4; j++) {
            const int row = r0 + j * 64;
            const __half* gb = Bg + (size_t)row * K + kc * 8;
            asm volatile("cp.async.cg.shared.global [%0], [%1], 16;"
                         :: "r"(Bb + so0 + (uint32_t)(j * 64 * HLD * 2)), "l"(gb));
        }
    };

    issue(0, 0);
    asm volatile("cp.async.commit_group;" ::: "memory");
    if (nch > 1) issue(1, 1);
    asm volatile("cp.async.commit_group;" ::: "memory");

    const int g = lane >> 2;
    const int t = lane & 3;

    int st = 0;
    for (int i = 0; i < nch; i++) {
        asm volatile("cp.async.wait_group 1;" ::: "memory");
        __syncthreads();

        const __half* Ac = smh + st * A_ST;
        const __half* Bc = smh + NSTAGE * A_ST + st * B_ST;
#pragma unroll
        for (int kk = 0; kk < 2; kk++) {
            const int kb = kk * 16 + 2 * t;
            uint32_t af[4][4];
#pragma unroll
            for (int mt = 0; mt < 4; mt++) {
                const int mrow = wm * 64 + mt * 16 + g;
                af[mt][0] = *(const uint32_t*)&Ac[(mrow    ) * HLD + kb    ];
                af[mt][1] = *(const uint32_t*)&Ac[(mrow + 8) * HLD + kb    ];
                af[mt][2] = *(const uint32_t*)&Ac[(mrow    ) * HLD + kb + 8];
                af[mt][3] = *(const uint32_t*)&Ac[(mrow + 8) * HLD + kb + 8];
            }
#pragma unroll
            for (int nt = 0; nt < 8; nt++) {
                const int nrow = wn * 64 + nt * 8 + g;
                uint32_t b0 = *(const uint32_t*)&Bc[nrow * HLD + kb    ];
                uint32_t b1 = *(const uint32_t*)&Bc[nrow * HLD + kb + 8];
#pragma unroll
                for (int mt = 0; mt < 4; mt++)
                    mma_f16(acc[mt][nt], af[mt][0], af[mt][1], af[mt][2], af[mt][3],
                            b0, b1);
            }
        }

        __syncthreads();
        if (i + 2 < nch) issue(i + 2, (st + 2) % NSTAGE);
        asm volatile("cp.async.commit_group;" ::: "memory");
        st = (st + 1) % NSTAGE;
    }

    // epilogue
    const int c2 = t * 2;
#pragma unroll
    for (int mt = 0; mt < 4; mt++) {
#pragma unroll
        for (int nt = 0; nt < 8; nt++) {
            int row = bm + wm * 64 + mt * 16 + g;
            int col = bn + wn * 64 + nt * 8 + c2;
            float v0 = acc[mt][nt][0], v1 = acc[mt][nt][1];
            float v2 = acc[mt][nt][2], v3 = acc[mt][nt][3];
            if (BIAS_RELU) {
                float bb0 = bias[col], bb1 = bias[col + 1];
                v0 = fmaxf(v0 + bb0, 0.0f); v1 = fmaxf(v1 + bb1, 0.0f);
                v2 = fmaxf(v2 + bb0, 0.0f); v3 = fmaxf(v3 + bb1, 0.0f);
            }
            if (OUT_HALF) {
                __half* C = (__half*)Cv;
                *(__half2*)&C[(size_t)row * N + col]       = __floats2half2_rn(v0, v1);
                *(__half2*)&C[(size_t)(row + 8) * N + col] = __floats2half2_rn(v2, v3);
            } else {
                float* C = (float*)Cv;
                *(float2*)&C[(size_t)row * N + col]       = make_float2(v0, v1);
                *(float2*)&C[(size_t)(row + 8) * N + col] = make_float2(v2, v3);
            }
        }
    }
}

// small GEMM: C[NN,10] = A_h[NN,1024] @ B[1024,10]; W3 staged in smem
__global__ void sgemm_small_h(const __half* __restrict__ A, const float* __restrict__ B,
                              float* __restrict__ C) {
    __shared__ float Ws[H2D * F_OUT];
    int tid = threadIdx.y * F_OUT + threadIdx.x;
    for (int i = tid; i < H2D * F_OUT; i += F_OUT * 16) Ws[i] = B[i];
    __syncthreads();
    int m = blockIdx.x * 16 + threadIdx.y;
    int n = threadIdx.x;
    const uint4* a = (const uint4*)(A + (size_t)m * H2D);
    float s = 0.0f;
#pragma unroll 4
    for (int k8 = 0; k8 < H2D / 8; k8++) {
        uint4 v = a[k8];
        float2 f0 = __half22float2(*(__half2*)&v.x);
        float2 f1 = __half22float2(*(__half2*)&v.y);
        float2 f2 = __half22float2(*(__half2*)&v.z);
        float2 f3 = __half22float2(*(__half2*)&v.w);
        int k = k8 * 8;
        s += f0.x * Ws[(k + 0) * F_OUT + n] + f0.y * Ws[(k + 1) * F_OUT + n];
        s += f1.x * Ws[(k + 2) * F_OUT + n] + f1.y * Ws[(k + 3) * F_OUT + n];
        s += f2.x * Ws[(k + 4) * F_OUT + n] + f2.y * Ws[(k + 5) * F_OUT + n];
        s += f3.x * Ws[(k + 6) * F_OUT + n] + f3.y * Ws[(k + 7) * F_OUT + n];
    }
    C[m * F_OUT + n] = s;
}

// final: out = log_softmax(a3 + b3)
__global__ void k_logsoftmax(const float* __restrict__ a3, const float* __restrict__ b3,
                             float* __restrict__ out) {
    int m = blockIdx.x * blockDim.x + threadIdx.x;
    if (m >= NN) return;
    float v[F_OUT];
    float mx = -1e30f;
#pragma unroll
    for (int n = 0; n < F_OUT; n++) {
        v[n] = a3[m * F_OUT + n] + b3[n];
        mx = fmaxf(mx, v[n]);
    }
    float s = 0.0f;
#pragma unroll
    for (int n = 0; n < F_OUT; n++) s += expf(v[n] - mx);
    float lse = mx + logf(s);
#pragma unroll
    for (int n = 0; n < F_OUT; n++) out[m * F_OUT + n] = v[n] - lse;
}

// ---------------- launch ----------------
extern "C" void kernel_launch(void* const* d_in, const int* in_sizes, int n_in,
                              void* d_out, int out_size) {
    const float* x  = (const float*)d_in[0];
    const float* W1 = (const float*)d_in[1];
    const float* b1 = (const float*)d_in[2];
    const float* W2 = (const float*)d_in[3];
    const float* b2 = (const float*)d_in[4];
    const float* W3 = (const float*)d_in[5];
    const float* b3 = (const float*)d_in[6];
    const void*  ei = d_in[7];
    float* out = (float*)d_out;

    float *t3, *a3;
    __half *aggxh, *w1t, *w2t, *h1h, *t2h, *h2h;
    cudaGetSymbolAddress((void**)&aggxh, g_aggxh);
    cudaGetSymbolAddress((void**)&w1t,   g_w1t);
    cudaGetSymbolAddress((void**)&w2t,   g_w2t);
    cudaGetSymbolAddress((void**)&h1h,   g_h1h);
    cudaGetSymbolAddress((void**)&t2h,   g_t2h);
    cudaGetSymbolAddress((void**)&h2h,   g_h2h);
    cudaGetSymbolAddress((void**)&t3,    g_t3);
    cudaGetSymbolAddress((void**)&a3,    g_a3);

    cudaFuncSetAttribute(hgemm<true, true>,  cudaFuncAttributeMaxDynamicSharedMemorySize, GEMM_SMEM);
    cudaFuncSetAttribute(hgemm<false, true>, cudaFuncAttributeMaxDynamicSharedMemorySize, GEMM_SMEM);

    // weight transposes (independent of graph preprocessing)
    {
        dim3 blk(32, 8);
        dim3 g1(H1D / 32, F_IN / 32);
        k_transpose_h<<<g1, blk>>>(W1, w1t, F_IN, H1D);
        dim3 g2(H2D / 32, H1D / 32);
        k_transpose_h<<<g2, blk>>>(W2, w2t, H1D, H2D);
    }

    // graph preprocessing: degrees, norms, CSR by destination
    k_deg_init<<<(NN + 255) / 256, 256>>>(ei);
    k_deg_count<<<(EE + 255) / 256, 256>>>(ei);
    k_dinv<<<(NN + 255) / 256, 256>>>();
    k_edge_prep<<<(EE + 255) / 256, 256>>>(ei);
    k_scan<<<1, 256>>>();
    k_place<<<(EE + 255) / 256, 256>>>();

    // ---- layer 1: CSR gather (fp32 -> fp16), GEMM + fused bias/relu (fp16 out)
    {
        k_gather1<<<NN, 128>>>(x, aggxh);
        dim3 grid(H1D / 256, NN / 128);
        hgemm<true, true><<<grid, 256, GEMM_SMEM>>>(aggxh, w1t, b1, h1h, NN, H1D, F_IN);
    }

    // ---- layer 2: GEMM (4096 -> 1024, fp16 out), CSR gather + fused bias/relu (fp16)
    {
        dim3 grid(H2D / 256, NN / 128);
        hgemm<false, true><<<grid, 256, GEMM_SMEM>>>(h1h, w2t, nullptr, t2h, NN, H2D, H1D);
        k_gather2h<<<NN, 256>>>(t2h, b2, h2h);
    }

    // ---- layer 3: small GEMM (1024 -> 10), gather, bias + log_softmax
    {
        dim3 blk(F_OUT, 16);
        sgemm_small_h<<<NN / 16, blk>>>(h2h, W3, t3);
        k_gather3<<<(NN * F_OUT + 255) / 256, 256>>>(t3, a3);
        k_logsoftmax<<<(NN + 255) / 256, 256>>>(a3, b3, out);
    }
}

// round 10
// speedup vs baseline: 1.0551x; 1.0551x over previous
#include <cuda_runtime.h>
#include <cuda_fp16.h>
#include <cuda_bf16.h>
#include <math.h>
#include <stdint.h>

// Problem constants (fixed by the dataset)
#define NN 8192
#define EE 65536
#define F_IN 512
#define H1D 4096
#define H2D 1024
#define F_OUT 10

// ---------------- scratch (device globals: allocation-free) ----------------
__device__ int    g_is64;
__device__ float  g_deg[NN];
__device__ float  g_dinv[NN];
__device__ int    g_src[EE];
__device__ int    g_dst[EE];
__device__ float  g_norm[EE];
__device__ int    g_rowstart[NN + 1];
__device__ int    g_cursor[NN];
__device__ int    g_csrc[EE];
__device__ float  g_cnorm[EE];
__device__ __half g_aggxh[(size_t)NN * F_IN];    // fp16 aggregated x
__device__ __half g_w1t[(size_t)H1D * F_IN];     // W1^T fp16 [4096][512]
__device__ __half g_w2t[(size_t)H2D * H1D];      // W2^T fp16 [1024][4096]
__device__ __half g_h1h[(size_t)NN * H1D];       // layer1 out fp16
__device__ __half g_t2h[(size_t)NN * H2D];       // h1 @ W2 fp16
__device__ __half g_h2h[(size_t)NN * H2D];       // relu(A t2 + b2) fp16
__device__ float  g_t3[(size_t)NN * F_OUT];
__device__ float  g_a3[(size_t)NN * F_OUT];

// ---------------- graph preprocessing ----------------
__device__ __forceinline__ int edge_val(const void* ei, int idx) {
    if (g_is64) return (int)((const long long*)ei)[idx];
    return ((const int*)ei)[idx];
}

// deg init + dtype probe in one kernel (probe in block 0, thread 0)
__global__ void k_deg_init(const void* __restrict__ ei) {
    int i = blockIdx.x * blockDim.x + threadIdx.x;
    if (i < NN) g_deg[i] = 1.0f;
    if (i == 0) {
        const long long* p = (const long long*)ei;
        int ok64 = 1;
        for (int j = 0; j < 64; j++) {
            long long v = p[j];
            if (v < 0 || v >= NN) { ok64 = 0; break; }
        }
        g_is64 = ok64;
    }
}

__global__ void k_deg_count(const void* __restrict__ ei) {
    int e = blockIdx.x * blockDim.x + threadIdx.x;
    if (e < EE) atomicAdd(&g_deg[edge_val(ei, EE + e)], 1.0f);
}

__global__ void k_dinv() {
    int i = blockIdx.x * blockDim.x + threadIdx.x;
    if (i < NN) g_dinv[i] = rsqrtf(g_deg[i]);
}

__global__ void k_edge_prep(const void* __restrict__ ei) {
    int e = blockIdx.x * blockDim.x + threadIdx.x;
    if (e < EE) {
        int s = edge_val(ei, e);
        int d = edge_val(ei, EE + e);
        g_src[e] = s;
        g_dst[e] = d;
        g_norm[e] = g_dinv[s] * g_dinv[d];
    }
}

// exclusive scan of (deg-1) over NN nodes; 1 block, 256 threads, 32 nodes each
__global__ void k_scan() {
    __shared__ int part[256];
    int t = threadIdx.x;
    int base = t * 32;
    int cnt[32];
    int s = 0;
#pragma unroll
    for (int i = 0; i < 32; i++) {
        cnt[i] = (int)g_deg[base + i] - 1;
        s += cnt[i];
    }
    part[t] = s;
    __syncthreads();
    for (int off = 1; off < 256; off <<= 1) {
        int v = (t >= off) ? part[t - off] : 0;
        __syncthreads();
        part[t] += v;
        __syncthreads();
    }
    int run = (t > 0) ? part[t - 1] : 0;
#pragma unroll
    for (int i = 0; i < 32; i++) {
        g_rowstart[base + i] = run;
        g_cursor[base + i] = 0;
        run += cnt[i];
    }
    if (t == 255) g_rowstart[NN] = run;
}

__global__ void k_place() {
    int e = blockIdx.x * blockDim.x + threadIdx.x;
    if (e >= EE) return;
    int d = g_dst[e];
    int pos = g_rowstart[d] + atomicAdd(&g_cursor[d], 1);
    g_csrc[pos]  = g_src[e];
    g_cnorm[pos] = g_norm[e];
}

// ---------------- CSR gather aggregation ----------------
// layer 1: out[r,:] = dinv^2 * x[r,:] + sum norm * x[src,:]   -> fp16 out
__global__ void k_gather1(const float* __restrict__ x, __half* __restrict__ out) {
    const int r = blockIdx.x;
    const int f = threadIdx.x;             // 0..127 (float4 lanes, F=512)
    const int s0 = g_rowstart[r], s1 = g_rowstart[r + 1];
    float di = g_dinv[r];
    float self = di * di;
    float4 v = ((const float4*)x)[(size_t)r * 128 + f];
    float4 acc = make_float4(v.x * self, v.y * self, v.z * self, v.w * self);
    for (int i = s0; i < s1; i++) {
        int src = g_csrc[i];
        float nrm = g_cnorm[i];
        float4 u = ((const float4*)x)[(size_t)src * 128 + f];
        acc.x += nrm * u.x; acc.y += nrm * u.y;
        acc.z += nrm * u.z; acc.w += nrm * u.w;
    }
    __half2 h0 = __floats2half2_rn(acc.x, acc.y);
    __half2 h1 = __floats2half2_rn(acc.z, acc.w);
    uint2 p;
    p.x = *(uint32_t*)&h0;
    p.y = *(uint32_t*)&h1;
    ((uint2*)out)[(size_t)r * 128 + f] = p;
}

// layer 2 (fp16 in/out): out[r,:] = relu( dinv^2*t2[r,:] + sum norm*t2[src,:] + bias )
__global__ void k_gather2h(const __half* __restrict__ t2, const float* __restrict__ bias,
                           __half* __restrict__ out) {
    const int r = blockIdx.x;
    const int f = threadIdx.x;             // 0..255 (4-half lanes, F=1024)
    const int s0 = g_rowstart[r], s1 = g_rowstart[r + 1];
    float di = g_dinv[r];
    float self = di * di;
    uint2 v = ((const uint2*)t2)[(size_t)r * 256 + f];
    float2 f0 = __half22float2(*(__half2*)&v.x);
    float2 f1 = __half22float2(*(__half2*)&v.y);
    float4 acc = make_float4(f0.x * self, f0.y * self, f1.x * self, f1.y * self);
    for (int i = s0; i < s1; i++) {
        int src = g_csrc[i];
        float nrm = g_cnorm[i];
        uint2 u = ((const uint2*)t2)[(size_t)src * 256 + f];
        float2 u0 = __half22float2(*(__half2*)&u.x);
        float2 u1 = __half22float2(*(__half2*)&u.y);
        acc.x += nrm * u0.x; acc.y += nrm * u0.y;
        acc.z += nrm * u1.x; acc.w += nrm * u1.y;
    }
    float4 b = ((const float4*)bias)[f];
    acc.x = fmaxf(acc.x + b.x, 0.0f);
    acc.y = fmaxf(acc.y + b.y, 0.0f);
    acc.z = fmaxf(acc.z + b.z, 0.0f);
    acc.w = fmaxf(acc.w + b.w, 0.0f);
    __half2 o0 = __floats2half2_rn(acc.x, acc.y);
    __half2 o1 = __floats2half2_rn(acc.z, acc.w);
    uint2 p;
    p.x = *(uint32_t*)&o0;
    p.y = *(uint32_t*)&o1;
    ((uint2*)out)[(size_t)r * 256 + f] = p;
}

// layer 3: scalar gather at F=10
__global__ void k_gather3(const float* __restrict__ t3, float* __restrict__ out) {
    int idx = blockIdx.x * blockDim.x + threadIdx.x;
    if (idx >= NN * F_OUT) return;
    int r = idx / F_OUT;
    int f = idx - r * F_OUT;
    const int s0 = g_rowstart[r], s1 = g_rowstart[r + 1];
    float di = g_dinv[r];
    float acc = di * di * t3[(size_t)r * F_OUT + f];
    for (int i = s0; i < s1; i++)
        acc += g_cnorm[i] * t3[(size_t)g_csrc[i] * F_OUT + f];
    out[idx] = acc;
}

// ---------------- transpose + convert: in[R][C] fp32 -> out[C][R] fp16 ----------------
__global__ void k_transpose_h(const float* __restrict__ in, __half* __restrict__ out,
                              int R, int C) {
    __shared__ float t[32][33];
    int c0 = blockIdx.x * 32, r0 = blockIdx.y * 32;
#pragma unroll
    for (int i = threadIdx.y; i < 32; i += 8)
        t[i][threadIdx.x] = in[(size_t)(r0 + i) * C + c0 + threadIdx.x];
    __syncthreads();
#pragma unroll
    for (int i = threadIdx.y; i < 32; i += 8)
        out[(size_t)(c0 + i) * R + r0 + threadIdx.x] = __float2half(t[threadIdx.x][i]);
}

// ---------------- FP16 tensor-core GEMM, cp.async 3-stage pipeline ----------------
// C[M,N] = A[M,K] @ B[N,K]^T : A, B fp16 k-contiguous.
// Block 256(M) x 128(N), K-chunk 32, 512 threads = 16 warps (4M x 4N), warp 64x32.
// Warp-level inner loop identical to the known-good R8 configuration.

#define HLD 40                           // halves per smem row (32 + 8 pad)
#define A_ST (256 * HLD)                 // A halves per stage (10240)
#define B_ST (128 * HLD)                 // B halves per stage (5120)
#define NSTAGE 3
#define GEMM_SMEM (NSTAGE * (A_ST + B_ST) * 2)   // 92160 bytes

__device__ __forceinline__ uint32_t smem_u32(const void* p) {
    uint32_t a;
    asm("{ .reg .u64 t; cvta.to.shared.u64 t, %1; cvt.u32.u64 %0, t; }" : "=r"(a) : "l"(p));
    return a;
}

__device__ __forceinline__ void mma_f16(float c[4], uint32_t a0, uint32_t a1,
                                        uint32_t a2, uint32_t a3,
                                        uint32_t b0, uint32_t b1) {
    asm volatile(
        "mma.sync.aligned.m16n8k16.row.col.f32.f16.f16.f32 "
        "{%0,%1,%2,%3}, {%4,%5,%6,%7}, {%8,%9}, {%0,%1,%2,%3};"
        : "+f"(c[0]), "+f"(c[1]), "+f"(c[2]), "+f"(c[3])
        : "r"(a0), "r"(a1), "r"(a2), "r"(a3), "r"(b0), "r"(b1));
}

template<bool BIAS_RELU, bool OUT_HALF>
__global__ __launch_bounds__(512, 1)
void hgemm(const __half* __restrict__ A, const __half* __restrict__ B,
           const float* __restrict__ bias, void* __restrict__ Cv,
           int M, int N, int K) {
    extern __shared__ __half smh[];
    const uint32_t sb = smem_u32(smh);

    const int tid  = threadIdx.x;
    const int lane = tid & 31;
    const int w    = tid >> 5;            // 0..15
    const int wm   = w >> 2;              // 0..3  (64-row slab)
    const int wn   = w & 3;               // 0..3  (32-col slab)
    const int bm   = blockIdx.y * 256;
    const int bn   = blockIdx.x * 128;

    // cp.async mapping: A 1024 16B-chunks (256 rows x 4), B 512 chunks (128 x 4)
    // 512 threads: A 2 chunks/thread, B 1 chunk/thread.
    const int r0 = tid >> 2;              // 0..127
    const int kc = tid & 3;               // 8-half group

    float acc[4][4][4];
#pragma unroll
    for (int i = 0; i < 4; i++)
#pragma unroll
        for (int j = 0; j < 4; j++)
#pragma unroll
            for (int r = 0; r < 4; r++) acc[i][j][r] = 0.0f;

    const int nch = K >> 5;

    auto issue = [&](int chunk, int s) {
        const __half* Ag = A + (size_t)bm * K + chunk * 32;
        const __half* Bg = B + (size_t)bn * K + chunk * 32;
        const uint32_t Ab = sb + s * (A_ST * 2);
        const uint32_t Bb = sb + (NSTAGE * A_ST + s * B_ST) * 2;
        const uint32_t so0 = (uint32_t)(r0 * HLD + kc * 8) * 2;
#pragma unroll
        for (int j = 0; j < 2; j++) {
            const int row = r0 + j * 128;
            const __half* ga = Ag + (size_t)row * K + kc * 8;
            asm volatile("cp.async.cg.shared.global [%0], [%1], 16;"
                         :: "r"(Ab + so0 + (uint32_t)(j * 128 * HLD * 2)), "l"(ga));
        }
        {
            const __half* gb = Bg + (size_t)r0 * K + kc * 8;
            asm volatile("cp.async.cg.shared.global [%0], [%1], 16;"
                         :: "r"(Bb + so0), "l"(gb));
        }
    };

    issue(0, 0);
    asm volatile("cp.async.commit_group;" ::: "memory");
    if (nch > 1) issue(1, 1);
    asm volatile("cp.async.commit_group;" ::: "memory");

    const int g = lane >> 2;
    const int t = lane & 3;

    int st = 0;
    for (int i = 0; i < nch; i++) {
        asm volatile("cp.async.wait_group 1;" ::: "memory");
        __syncthreads();

        const __half* Ac = smh + st * A_ST;
        const __half* Bc = smh + NSTAGE * A_ST + st * B_ST;
#pragma unroll
        for (int kk = 0; kk < 2; kk++) {
            const int kb = kk * 16 + 2 * t;
            uint32_t af[4][4];
#pragma unroll
            for (int mt = 0; mt < 4; mt++) {
                const int mrow = wm * 64 + mt * 16 + g;
                af[mt][0] = *(const uint32_t*)&Ac[(mrow    ) * HLD + kb    ];
                af[mt][1] = *(const uint32_t*)&Ac[(mrow + 8) * HLD + kb    ];
                af[mt][2] = *(const uint32_t*)&Ac[(mrow    ) * HLD + kb + 8];
                af[mt][3] = *(const uint32_t*)&Ac[(mrow + 8) * HLD + kb + 8];
            }
            uint32_t bf[4][2];
#pragma unroll
            for (int nt = 0; nt < 4; nt++) {
                const int nrow = wn * 32 + nt * 8 + g;
                bf[nt][0] = *(const uint32_t*)&Bc[nrow * HLD + kb    ];
                bf[nt][1] = *(const uint32_t*)&Bc[nrow * HLD + kb + 8];
            }
#pragma unroll
            for (int mt = 0; mt < 4; mt++)
#pragma unroll
                for (int nt = 0; nt < 4; nt++)
                    mma_f16(acc[mt][nt], af[mt][0], af[mt][1], af[mt][2], af[mt][3],
                            bf[nt][0], bf[nt][1]);
        }

        __syncthreads();
        if (i + 2 < nch) issue(i + 2, (st + 2) % NSTAGE);
        asm volatile("cp.async.commit_group;" ::: "memory");
        st = (st + 1) % NSTAGE;
    }

    // epilogue
    const int c2 = t * 2;
#pragma unroll
    for (int mt = 0; mt < 4; mt++) {
#pragma unroll
        for (int nt = 0; nt < 4; nt++) {
            int row = bm + wm * 64 + mt * 16 + g;
            int col = bn + wn * 32 + nt * 8 + c2;
            float v0 = acc[mt][nt][0], v1 = acc[mt][nt][1];
            float v2 = acc[mt][nt][2], v3 = acc[mt][nt][3];
            if (BIAS_RELU) {
                float bb0 = bias[col], bb1 = bias[col + 1];
                v0 = fmaxf(v0 + bb0, 0.0f); v1 = fmaxf(v1 + bb1, 0.0f);
                v2 = fmaxf(v2 + bb0, 0.0f); v3 = fmaxf(v3 + bb1, 0.0f);
            }
            if (OUT_HALF) {
                __half* C = (__half*)Cv;
                *(__half2*)&C[(size_t)row * N + col]       = __floats2half2_rn(v0, v1);
                *(__half2*)&C[(size_t)(row + 8) * N + col] = __floats2half2_rn(v2, v3);
            } else {
                float* C = (float*)Cv;
                *(float2*)&C[(size_t)row * N + col]       = make_float2(v0, v1);
                *(float2*)&C[(size_t)(row + 8) * N + col] = make_float2(v2, v3);
            }
        }
    }
}

// small GEMM: C[NN,10] = A_h[NN,1024] @ B[1024,10]; W3 staged in smem
__global__ void sgemm_small_h(const __half* __restrict__ A, const float* __restrict__ B,
                              float* __restrict__ C) {
    __shared__ float Ws[H2D * F_OUT];
    int tid = threadIdx.y * F_OUT + threadIdx.x;
    for (int i = tid; i < H2D * F_OUT; i += F_OUT * 16) Ws[i] = B[i];
    __syncthreads();
    int m = blockIdx.x * 16 + threadIdx.y;
    int n = threadIdx.x;
    const uint4* a = (const uint4*)(A + (size_t)m * H2D);
    float s = 0.0f;
#pragma unroll 4
    for (int k8 = 0; k8 < H2D / 8; k8++) {
        uint4 v = a[k8];
        float2 f0 = __half22float2(*(__half2*)&v.x);
        float2 f1 = __half22float2(*(__half2*)&v.y);
        float2 f2 = __half22float2(*(__half2*)&v.z);
        float2 f3 = __half22float2(*(__half2*)&v.w);
        int k = k8 * 8;
        s += f0.x * Ws[(k + 0) * F_OUT + n] + f0.y * Ws[(k + 1) * F_OUT + n];
        s += f1.x * Ws[(k + 2) * F_OUT + n] + f1.y * Ws[(k + 3) * F_OUT + n];
        s += f2.x * Ws[(k + 4) * F_OUT + n] + f2.y * Ws[(k + 5) * F_OUT + n];
        s += f3.x * Ws[(k + 6) * F_OUT + n] + f3.y * Ws[(k + 7) * F_OUT + n];
    }
    C[m * F_OUT + n] = s;
}

// final: out = log_softmax(a3 + b3)
__global__ void k_logsoftmax(const float* __restrict__ a3, const float* __restrict__ b3,
                             float* __restrict__ out) {
    int m = blockIdx.x * blockDim.x + threadIdx.x;
    if (m >= NN) return;
    float v[F_OUT];
    float mx = -1e30f;
#pragma unroll
    for (int n = 0; n < F_OUT; n++) {
        v[n] = a3[m * F_OUT + n] + b3[n];
        mx = fmaxf(mx, v[n]);
    }
    float s = 0.0f;
#pragma unroll
    for (int n = 0; n < F_OUT; n++) s += expf(v[n] - mx);
    float lse = mx + logf(s);
#pragma unroll
    for (int n = 0; n < F_OUT; n++) out[m * F_OUT + n] = v[n] - lse;
}

// ---------------- launch ----------------
extern "C" void kernel_launch(void* const* d_in, const int* in_sizes, int n_in,
                              void* d_out, int out_size) {
    const float* x  = (const float*)d_in[0];
    const float* W1 = (const float*)d_in[1];
    const float* b1 = (const float*)d_in[2];
    const float* W2 = (const float*)d_in[3];
    const float* b2 = (const float*)d_in[4];
    const float* W3 = (const float*)d_in[5];
    const float* b3 = (const float*)d_in[6];
    const void*  ei = d_in[7];
    float* out = (float*)d_out;

    float *t3, *a3;
    __half *aggxh, *w1t, *w2t, *h1h, *t2h, *h2h;
    cudaGetSymbolAddress((void**)&aggxh, g_aggxh);
    cudaGetSymbolAddress((void**)&w1t,   g_w1t);
    cudaGetSymbolAddress((void**)&w2t,   g_w2t);
    cudaGetSymbolAddress((void**)&h1h,   g_h1h);
    cudaGetSymbolAddress((void**)&t2h,   g_t2h);
    cudaGetSymbolAddress((void**)&h2h,   g_h2h);
    cudaGetSymbolAddress((void**)&t3,    g_t3);
    cudaGetSymbolAddress((void**)&a3,    g_a3);

    cudaFuncSetAttribute(hgemm<true, true>,  cudaFuncAttributeMaxDynamicSharedMemorySize, GEMM_SMEM);
    cudaFuncSetAttribute(hgemm<false, true>, cudaFuncAttributeMaxDynamicSharedMemorySize, GEMM_SMEM);

    // weight transposes (independent of graph preprocessing)
    {
        dim3 blk(32, 8);
        dim3 g1(H1D / 32, F_IN / 32);
        k_transpose_h<<<g1, blk>>>(W1, w1t, F_IN, H1D);
        dim3 g2(H2D / 32, H1D / 32);
        k_transpose_h<<<g2, blk>>>(W2, w2t, H1D, H2D);
    }

    // graph preprocessing: degrees, norms, CSR by destination
    k_deg_init<<<(NN + 255) / 256, 256>>>(ei);
    k_deg_count<<<(EE + 255) / 256, 256>>>(ei);
    k_dinv<<<(NN + 255) / 256, 256>>>();
    k_edge_prep<<<(EE + 255) / 256, 256>>>(ei);
    k_scan<<<1, 256>>>();
    k_place<<<(EE + 255) / 256, 256>>>();

    // ---- layer 1: CSR gather (fp32 -> fp16), GEMM + fused bias/relu (fp16 out)
    {
        k_gather1<<<NN, 128>>>(x, aggxh);
        dim3 grid(H1D / 128, NN / 256);
        hgemm<true, true><<<grid, 512, GEMM_SMEM>>>(aggxh, w1t, b1, h1h, NN, H1D, F_IN);
    }

    // ---- layer 2: GEMM (4096 -> 1024, fp16 out), CSR gather + fused bias/relu (fp16)
    {
        dim3 grid(H2D / 128, NN / 256);
        hgemm<false, true><<<grid, 512, GEMM_SMEM>>>(h1h, w2t, nullptr, t2h, NN, H2D, H1D);
        k_gather2h<<<NN, 256>>>(t2h, b2, h2h);
    }

    // ---- layer 3: small GEMM (1024 -> 10), gather, bias + log_softmax
    {
        dim3 blk(F_OUT, 16);
        sgemm_small_h<<<NN / 16, blk>>>(h2h, W3, t3);
        k_gather3<<<(NN * F_OUT + 255) / 256, 256>>>(t3, a3);
        k_logsoftmax<<<(NN + 255) / 256, 256>>>(a3, b3, out);
    }
}

// round 12
// speedup vs baseline: 1.0624x; 1.0069x over previous
#include <cuda_runtime.h>
#include <cuda_fp16.h>
#include <cuda_bf16.h>
#include <math.h>
#include <stdint.h>

// Problem constants (fixed by the dataset)
#define NN 8192
#define EE 65536
#define F_IN 512
#define H1D 4096
#define H2D 1024
#define F_OUT 10

// ---------------- scratch (device globals: allocation-free) ----------------
__device__ int    g_is64;
__device__ float  g_deg[NN];
__device__ float  g_dinv[NN];
__device__ int    g_src[EE];
__device__ int    g_dst[EE];
__device__ float  g_norm[EE];
__device__ int    g_rowstart[NN + 1];
__device__ int    g_cursor[NN];
__device__ int    g_csrc[EE];
__device__ float  g_cnorm[EE];
__device__ __half g_aggxh[(size_t)NN * F_IN];    // fp16 aggregated x
__device__ __half g_w1t[(size_t)H1D * F_IN];     // W1^T fp16 [4096][512]
__device__ __half g_w2t[(size_t)H2D * H1D];      // W2^T fp16 [1024][4096]
__device__ __half g_h1h[(size_t)NN * H1D];       // layer1 out fp16
__device__ __half g_t2h[(size_t)NN * H2D];       // h1 @ W2 fp16
__device__ __half g_h2h[(size_t)NN * H2D];       // relu(A t2 + b2) fp16
__device__ float  g_t3[(size_t)NN * F_OUT];

// ---------------- graph preprocessing ----------------
__device__ __forceinline__ int edge_val(const void* ei, int idx) {
    if (g_is64) return (int)((const long long*)ei)[idx];
    return ((const int*)ei)[idx];
}

// deg init + dtype probe in one kernel (probe in block 0, thread 0)
__global__ void k_deg_init(const void* __restrict__ ei) {
    int i = blockIdx.x * blockDim.x + threadIdx.x;
    if (i < NN) g_deg[i] = 1.0f;
    if (i == 0) {
        const long long* p = (const long long*)ei;
        int ok64 = 1;
        for (int j = 0; j < 64; j++) {
            long long v = p[j];
            if (v < 0 || v >= NN) { ok64 = 0; break; }
        }
        g_is64 = ok64;
    }
}

__global__ void k_deg_count(const void* __restrict__ ei) {
    int e = blockIdx.x * blockDim.x + threadIdx.x;
    if (e < EE) atomicAdd(&g_deg[edge_val(ei, EE + e)], 1.0f);
}

// fused: dinv (i < NN) + edge src/dst/norm (e < EE); both depend only on g_deg
__global__ void k_prep(const void* __restrict__ ei) {
    int e = blockIdx.x * blockDim.x + threadIdx.x;
    if (e < NN) g_dinv[e] = rsqrtf(g_deg[e]);
    if (e < EE) {
        int s = edge_val(ei, e);
        int d = edge_val(ei, EE + e);
        g_src[e] = s;
        g_dst[e] = d;
        g_norm[e] = rsqrtf(g_deg[s]) * rsqrtf(g_deg[d]);
    }
}

// exclusive scan of (deg-1) over NN nodes; 1 block, 256 threads, 32 nodes each
__global__ void k_scan() {
    __shared__ int part[256];
    int t = threadIdx.x;
    int base = t * 32;
    int cnt[32];
    int s = 0;
#pragma unroll
    for (int i = 0; i < 32; i++) {
        cnt[i] = (int)g_deg[base + i] - 1;
        s += cnt[i];
    }
    part[t] = s;
    __syncthreads();
    for (int off = 1; off < 256; off <<= 1) {
        int v = (t >= off) ? part[t - off] : 0;
        __syncthreads();
        part[t] += v;
        __syncthreads();
    }
    int run = (t > 0) ? part[t - 1] : 0;
#pragma unroll
    for (int i = 0; i < 32; i++) {
        g_rowstart[base + i] = run;
        g_cursor[base + i] = 0;
        run += cnt[i];
    }
    if (t == 255) g_rowstart[NN] = run;
}

__global__ void k_place() {
    int e = blockIdx.x * blockDim.x + threadIdx.x;
    if (e >= EE) return;
    int d = g_dst[e];
    int pos = g_rowstart[d] + atomicAdd(&g_cursor[d], 1);
    g_csrc[pos]  = g_src[e];
    g_cnorm[pos] = g_norm[e];
}

// ---------------- CSR gather aggregation ----------------
// layer 1: out[r,:] = dinv^2 * x[r,:] + sum norm * x[src,:]   -> fp16 out
__global__ void k_gather1(const float* __restrict__ x, __half* __restrict__ out) {
    const int r = blockIdx.x;
    const int f = threadIdx.x;             // 0..127 (float4 lanes, F=512)
    const int s0 = g_rowstart[r], s1 = g_rowstart[r + 1];
    float di = g_dinv[r];
    float self = di * di;
    float4 v = ((const float4*)x)[(size_t)r * 128 + f];
    float4 acc = make_float4(v.x * self, v.y * self, v.z * self, v.w * self);
    for (int i = s0; i < s1; i++) {
        int src = g_csrc[i];
        float nrm = g_cnorm[i];
        float4 u = ((const float4*)x)[(size_t)src * 128 + f];
        acc.x += nrm * u.x; acc.y += nrm * u.y;
        acc.z += nrm * u.z; acc.w += nrm * u.w;
    }
    __half2 h0 = __floats2half2_rn(acc.x, acc.y);
    __half2 h1 = __floats2half2_rn(acc.z, acc.w);
    uint2 p;
    p.x = *(uint32_t*)&h0;
    p.y = *(uint32_t*)&h1;
    ((uint2*)out)[(size_t)r * 128 + f] = p;
}

// layer 2 (fp16 in/out): out[r,:] = relu( dinv^2*t2[r,:] + sum norm*t2[src,:] + bias )
__global__ void k_gather2h(const __half* __restrict__ t2, const float* __restrict__ bias,
                           __half* __restrict__ out) {
    const int r = blockIdx.x;
    const int f = threadIdx.x;             // 0..255 (4-half lanes, F=1024)
    const int s0 = g_rowstart[r], s1 = g_rowstart[r + 1];
    float di = g_dinv[r];
    float self = di * di;
    uint2 v = ((const uint2*)t2)[(size_t)r * 256 + f];
    float2 f0 = __half22float2(*(__half2*)&v.x);
    float2 f1 = __half22float2(*(__half2*)&v.y);
    float4 acc = make_float4(f0.x * self, f0.y * self, f1.x * self, f1.y * self);
    for (int i = s0; i < s1; i++) {
        int src = g_csrc[i];
        float nrm = g_cnorm[i];
        uint2 u = ((const uint2*)t2)[(size_t)src * 256 + f];
        float2 u0 = __half22float2(*(__half2*)&u.x);
        float2 u1 = __half22float2(*(__half2*)&u.y);
        acc.x += nrm * u0.x; acc.y += nrm * u0.y;
        acc.z += nrm * u1.x; acc.w += nrm * u1.y;
    }
    float4 b = ((const float4*)bias)[f];
    acc.x = fmaxf(acc.x + b.x, 0.0f);
    acc.y = fmaxf(acc.y + b.y, 0.0f);
    acc.z = fmaxf(acc.z + b.z, 0.0f);
    acc.w = fmaxf(acc.w + b.w, 0.0f);
    __half2 o0 = __floats2half2_rn(acc.x, acc.y);
    __half2 o1 = __floats2half2_rn(acc.z, acc.w);
    uint2 p;
    p.x = *(uint32_t*)&o0;
    p.y = *(uint32_t*)&o1;
    ((uint2*)out)[(size_t)r * 256 + f] = p;
}

// layer 3 fused: gather (F=10) + bias + log_softmax, 16 rows per block (160 thr)
__global__ void k_g3_lsm(const float* __restrict__ t3, const float* __restrict__ b3,
                         float* __restrict__ out) {
    __shared__ float sv[16][F_OUT];
    __shared__ float slse[16];
    const int ty = threadIdx.x / F_OUT;    // 0..15
    const int f  = threadIdx.x % F_OUT;    // 0..9
    const int r  = blockIdx.x * 16 + ty;
    const int s0 = g_rowstart[r], s1 = g_rowstart[r + 1];
    float di = g_dinv[r];
    float acc = di * di * t3[(size_t)r * F_OUT + f];
    for (int i = s0; i < s1; i++)
        acc += g_cnorm[i] * t3[(size_t)g_csrc[i] * F_OUT + f];
    acc += b3[f];
    sv[ty][f] = acc;
    __syncthreads();
    if (f == 0) {
        float mx = -1e30f;
#pragma unroll
        for (int n = 0; n < F_OUT; n++) mx = fmaxf(mx, sv[ty][n]);
        float s = 0.0f;
#pragma unroll
        for (int n = 0; n < F_OUT; n++) s += expf(sv[ty][n] - mx);
        slse[ty] = mx + logf(s);
    }
    __syncthreads();
    out[(size_t)r * F_OUT + f] = acc - slse[ty];
}

// ---------------- transpose + convert: in[R][C] fp32 -> out[C][R] fp16 ----------------
__global__ void k_transpose_h(const float* __restrict__ in, __half* __restrict__ out,
                              int R, int C) {
    __shared__ float t[32][33];
    int c0 = blockIdx.x * 32, r0 = blockIdx.y * 32;
#pragma unroll
    for (int i = threadIdx.y; i < 32; i += 8)
        t[i][threadIdx.x] = in[(size_t)(r0 + i) * C + c0 + threadIdx.x];
    __syncthreads();
#pragma unroll
    for (int i = threadIdx.y; i < 32; i += 8)
        out[(size_t)(c0 + i) * R + r0 + threadIdx.x] = __float2half(t[threadIdx.x][i]);
}

// ---------------- FP16 tensor-core GEMM, cp.async 4-stage pipeline ----------------
// (R8 128x128 config — known-good — with one extra pipeline stage.)
// C[M,N] = A[M,K] @ B[N,K]^T : A, B fp16 k-contiguous.
// Block 128x128, K-chunk 32, 256 threads = 8 warps (2M x 4N), warp 64x32.

#define HLD 40                         // halves per smem row (32 + 8 pad)
#define HSTAGE (128 * HLD)             // halves per operand per stage (5120)
#define NSTAGE 4
#define GEMM_SMEM (NSTAGE * HSTAGE * 2 * 2)   // 81920 bytes

__device__ __forceinline__ uint32_t smem_u32(const void* p) {
    uint32_t a;
    asm("{ .reg .u64 t; cvta.to.shared.u64 t, %1; cvt.u32.u64 %0, t; }" : "=r"(a) : "l"(p));
    return a;
}

__device__ __forceinline__ void mma_f16(float c[4], uint32_t a0, uint32_t a1,
                                        uint32_t a2, uint32_t a3,
                                        uint32_t b0, uint32_t b1) {
    asm volatile(
        "mma.sync.aligned.m16n8k16.row.col.f32.f16.f16.f32 "
        "{%0,%1,%2,%3}, {%4,%5,%6,%7}, {%8,%9}, {%0,%1,%2,%3};"
        : "+f"(c[0]), "+f"(c[1]), "+f"(c[2]), "+f"(c[3])
        : "r"(a0), "r"(a1), "r"(a2), "r"(a3), "r"(b0), "r"(b1));
}

template<bool BIAS_RELU, bool OUT_HALF>
__global__ __launch_bounds__(256, 2)
void hgemm(const __half* __restrict__ A, const __half* __restrict__ B,
           const float* __restrict__ bias, void* __restrict__ Cv,
           int M, int N, int K) {
    extern __shared__ __half smh[];
    const uint32_t sb = smem_u32(smh);

    const int tid  = threadIdx.x;
    const int lane = tid & 31;
    const int w    = tid >> 5;
    const int wm   = w >> 2;
    const int wn   = w & 3;
    const int bm   = blockIdx.y * 128;
    const int bn   = blockIdx.x * 128;

    // chunk mapping for cp.async: 512 16B-chunks per operand; thread does 2 + 2
    const int r0 = tid >> 2;            // rows 0..63 (and +64)
    const int kc = tid & 3;             // 8-half group

    float acc[4][4][4];
#pragma unroll
    for (int i = 0; i < 4; i++)
#pragma unroll
        for (int j = 0; j < 4; j++)
#pragma unroll
            for (int r = 0; r < 4; r++) acc[i][j][r] = 0.0f;

    const int nch = K >> 5;

    // byte offsets: A stage s at s*HSTAGE*2; B at (NSTAGE + s)*HSTAGE*2
    auto issue = [&](int chunk, int s) {
        const __half* Ag = A + (size_t)bm * K + chunk * 32;
        const __half* Bg = B + (size_t)bn * K + chunk * 32;
        const uint32_t Ab = sb + s * (HSTAGE * 2);
        const uint32_t Bb = sb + (NSTAGE + s) * (HSTAGE * 2);
#pragma unroll
        for (int j = 0; j < 2; j++) {
            const int row = r0 + j * 64;
            const uint32_t so = (uint32_t)(row * HLD + kc * 8) * 2;
            const __half* ga = Ag + (size_t)row * K + kc * 8;
            const __half* gb = Bg + (size_t)row * K + kc * 8;
            asm volatile("cp.async.cg.shared.global [%0], [%1], 16;" :: "r"(Ab + so), "l"(ga));
            asm volatile("cp.async.cg.shared.global [%0], [%1], 16;" :: "r"(Bb + so), "l"(gb));
        }
    };

    // prologue: 3 chunks in flight
    issue(0, 0);
    asm volatile("cp.async.commit_group;" ::: "memory");
    if (nch > 1) issue(1, 1);
    asm volatile("cp.async.commit_group;" ::: "memory");
    if (nch > 2) issue(2, 2);
    asm volatile("cp.async.commit_group;" ::: "memory");

    const int g = lane >> 2;
    const int t = lane & 3;

    int st = 0;
    for (int i = 0; i < nch; i++) {
        asm volatile("cp.async.wait_group 2;" ::: "memory");
        __syncthreads();

        const __half* Ac = smh + st * HSTAGE;
        const __half* Bc = smh + (NSTAGE + st) * HSTAGE;
#pragma unroll
        for (int kk = 0; kk < 2; kk++) {
            const int kb = kk * 16 + 2 * t;
            uint32_t af[4][4];
#pragma unroll
            for (int mt = 0; mt < 4; mt++) {
                const int mrow = wm * 64 + mt * 16 + g;
                af[mt][0] = *(const uint32_t*)&Ac[(mrow    ) * HLD + kb    ];
                af[mt][1] = *(const uint32_t*)&Ac[(mrow + 8) * HLD + kb    ];
                af[mt][2] = *(const uint32_t*)&Ac[(mrow    ) * HLD + kb + 8];
                af[mt][3] = *(const uint32_t*)&Ac[(mrow + 8) * HLD + kb + 8];
            }
            uint32_t bf[4][2];
#pragma unroll
            for (int nt = 0; nt < 4; nt++) {
                const int nrow = wn * 32 + nt * 8 + g;
                bf[nt][0] = *(const uint32_t*)&Bc[nrow * HLD + kb    ];
                bf[nt][1] = *(const uint32_t*)&Bc[nrow * HLD + kb + 8];
            }
#pragma unroll
            for (int mt = 0; mt < 4; mt++)
#pragma unroll
                for (int nt = 0; nt < 4; nt++)
                    mma_f16(acc[mt][nt], af[mt][0], af[mt][1], af[mt][2], af[mt][3],
                            bf[nt][0], bf[nt][1]);
        }

        __syncthreads();   // all warps done reading stage st before it is refilled
        if (i + 3 < nch) issue(i + 3, (st + 3) & (NSTAGE - 1));
        asm volatile("cp.async.commit_group;" ::: "memory");
        st = (st + 1) & (NSTAGE - 1);
    }

    // epilogue
    const int c2 = t * 2;
#pragma unroll
    for (int mt = 0; mt < 4; mt++) {
#pragma unroll
        for (int nt = 0; nt < 4; nt++) {
            int row = bm + wm * 64 + mt * 16 + g;
            int col = bn + wn * 32 + nt * 8 + c2;
            float v0 = acc[mt][nt][0], v1 = acc[mt][nt][1];
            float v2 = acc[mt][nt][2], v3 = acc[mt][nt][3];
            if (BIAS_RELU) {
                float bb0 = bias[col], bb1 = bias[col + 1];
                v0 = fmaxf(v0 + bb0, 0.0f); v1 = fmaxf(v1 + bb1, 0.0f);
                v2 = fmaxf(v2 + bb0, 0.0f); v3 = fmaxf(v3 + bb1, 0.0f);
            }
            if (OUT_HALF) {
                __half* C = (__half*)Cv;
                *(__half2*)&C[(size_t)row * N + col]       = __floats2half2_rn(v0, v1);
                *(__half2*)&C[(size_t)(row + 8) * N + col] = __floats2half2_rn(v2, v3);
            } else {
                float* C = (float*)Cv;
                *(float2*)&C[(size_t)row * N + col]       = make_float2(v0, v1);
                *(float2*)&C[(size_t)(row + 8) * N + col] = make_float2(v2, v3);
            }
        }
    }
}

// small GEMM: C[NN,10] = A_h[NN,1024] @ B[1024,10]; W3 staged in smem
__global__ void sgemm_small_h(const __half* __restrict__ A, const float* __restrict__ B,
                              float* __restrict__ C) {
    __shared__ float Ws[H2D * F_OUT];
    int tid = threadIdx.y * F_OUT + threadIdx.x;
    for (int i = tid; i < H2D * F_OUT; i += F_OUT * 16) Ws[i] = B[i];
    __syncthreads();
    int m = blockIdx.x * 16 + threadIdx.y;
    int n = threadIdx.x;
    const uint4* a = (const uint4*)(A + (size_t)m * H2D);
    float s = 0.0f;
#pragma unroll 4
    for (int k8 = 0; k8 < H2D / 8; k8++) {
        uint4 v = a[k8];
        float2 f0 = __half22float2(*(__half2*)&v.x);
        float2 f1 = __half22float2(*(__half2*)&v.y);
        float2 f2 = __half22float2(*(__half2*)&v.z);
        float2 f3 = __half22float2(*(__half2*)&v.w);
        int k = k8 * 8;
        s += f0.x * Ws[(k + 0) * F_OUT + n] + f0.y * Ws[(k + 1) * F_OUT + n];
        s += f1.x * Ws[(k + 2) * F_OUT + n] + f1.y * Ws[(k + 3) * F_OUT + n];
        s += f2.x * Ws[(k + 4) * F_OUT + n] + f2.y * Ws[(k + 5) * F_OUT + n];
        s += f3.x * Ws[(k + 6) * F_OUT + n] + f3.y * Ws[(k + 7) * F_OUT + n];
    }
    C[m * F_OUT + n] = s;
}

// ---------------- launch ----------------
extern "C" void kernel_launch(void* const* d_in, const int* in_sizes, int n_in,
                              void* d_out, int out_size) {
    const float* x  = (const float*)d_in[0];
    const float* W1 = (const float*)d_in[1];
    const float* b1 = (const float*)d_in[2];
    const float* W2 = (const float*)d_in[3];
    const float* b2 = (const float*)d_in[4];
    const float* W3 = (const float*)d_in[5];
    const float* b3 = (const float*)d_in[6];
    const void*  ei = d_in[7];
    float* out = (float*)d_out;

    float *t3;
    __half *aggxh, *w1t, *w2t, *h1h, *t2h, *h2h;
    cudaGetSymbolAddress((void**)&aggxh, g_aggxh);
    cudaGetSymbolAddress((void**)&w1t,   g_w1t);
    cudaGetSymbolAddress((void**)&w2t,   g_w2t);
    cudaGetSymbolAddress((void**)&h1h,   g_h1h);
    cudaGetSymbolAddress((void**)&t2h,   g_t2h);
    cudaGetSymbolAddress((void**)&h2h,   g_h2h);
    cudaGetSymbolAddress((void**)&t3,    g_t3);

    cudaFuncSetAttribute(hgemm<true, true>,  cudaFuncAttributeMaxDynamicSharedMemorySize, GEMM_SMEM);
    cudaFuncSetAttribute(hgemm<false, true>, cudaFuncAttributeMaxDynamicSharedMemorySize, GEMM_SMEM);

    // weight transposes (independent of graph preprocessing)
    {
        dim3 blk(32, 8);
        dim3 g1(H1D / 32, F_IN / 32);
        k_transpose_h<<<g1, blk>>>(W1, w1t, F_IN, H1D);
        dim3 g2(H2D / 32, H1D / 32);
        k_transpose_h<<<g2, blk>>>(W2, w2t, H1D, H2D);
    }

    // graph preprocessing: degrees, norms, CSR by destination
    k_deg_init<<<(NN + 255) / 256, 256>>>(ei);
    k_deg_count<<<(EE + 255) / 256, 256>>>(ei);
    k_prep<<<(EE + 255) / 256, 256>>>(ei);
    k_scan<<<1, 256>>>();
    k_place<<<(EE + 255) / 256, 256>>>();

    // ---- layer 1: CSR gather (fp32 -> fp16), GEMM + fused bias/relu (fp16 out)
    {
        k_gather1<<<NN, 128>>>(x, aggxh);
        dim3 grid(H1D / 128, NN / 128);
        hgemm<true, true><<<grid, 256, GEMM_SMEM>>>(aggxh, w1t, b1, h1h, NN, H1D, F_IN);
    }

    // ---- layer 2: GEMM (4096 -> 1024, fp16 out), CSR gather + fused bias/relu (fp16)
    {
        dim3 grid(H2D / 128, NN / 128);
        hgemm<false, true><<<grid, 256, GEMM_SMEM>>>(h1h, w2t, nullptr, t2h, NN, H2D, H1D);
        k_gather2h<<<NN, 256>>>(t2h, b2, h2h);
    }

    // ---- layer 3: small GEMM (1024 -> 10), fused gather + bias + log_softmax
    {
        dim3 blk(F_OUT, 16);
        sgemm_small_h<<<NN / 16, blk>>>(h2h, W3, t3);
        k_g3_lsm<<<NN / 16, 16 * F_OUT>>>(t3, b3, out);
    }
}

// round 14
// speedup vs baseline: 1.1171x; 1.0515x over previous
#include <cuda_runtime.h>
#include <cuda_fp16.h>
#include <cuda_bf16.h>
#include <math.h>
#include <stdint.h>

// Problem constants (fixed by the dataset)
#define NN 8192
#define EE 65536
#define F_IN 512
#define H1D 4096
#define H2D 1024
#define F_OUT 10

// ---------------- scratch (device globals: allocation-free) ----------------
__device__ int    g_is64;
__device__ float  g_deg[NN];
__device__ float  g_dinv[NN];
__device__ int    g_src[EE];
__device__ int    g_dst[EE];
__device__ float  g_norm[EE];
__device__ int    g_rowstart[NN + 1];
__device__ int    g_cursor[NN];
__device__ int    g_csrc[EE];
__device__ float  g_cnorm[EE];
__device__ __half g_aggxh[(size_t)NN * F_IN];    // fp16 aggregated x
__device__ __half g_w1t[(size_t)H1D * F_IN];     // W1^T fp16 [4096][512]
__device__ __half g_w2t[(size_t)H2D * H1D];      // W2^T fp16 [1024][4096]
__device__ __half g_h1h[(size_t)NN * H1D];       // layer1 out fp16
__device__ __half g_t2h[(size_t)NN * H2D];       // h1 @ W2 fp16
__device__ __half g_h2h[(size_t)NN * H2D];       // relu(A t2 + b2) fp16
__device__ float  g_t3[(size_t)NN * F_OUT];

// ---------------- graph preprocessing ----------------
__device__ __forceinline__ int edge_val(const void* ei, int idx) {
    if (g_is64) return (int)((const long long*)ei)[idx];
    return ((const int*)ei)[idx];
}

// deg init + dtype probe in one kernel (probe in block 0, thread 0)
__global__ void k_deg_init(const void* __restrict__ ei) {
    int i = blockIdx.x * blockDim.x + threadIdx.x;
    if (i < NN) g_deg[i] = 1.0f;
    if (i == 0) {
        const long long* p = (const long long*)ei;
        int ok64 = 1;
        for (int j = 0; j < 64; j++) {
            long long v = p[j];
            if (v < 0 || v >= NN) { ok64 = 0; break; }
        }
        g_is64 = ok64;
    }
}

__global__ void k_deg_count(const void* __restrict__ ei) {
    int e = blockIdx.x * blockDim.x + threadIdx.x;
    if (e < EE) atomicAdd(&g_deg[edge_val(ei, EE + e)], 1.0f);
}

// fused: dinv (i < NN) + edge src/dst/norm (e < EE); both depend only on g_deg
__global__ void k_prep(const void* __restrict__ ei) {
    int e = blockIdx.x * blockDim.x + threadIdx.x;
    if (e < NN) g_dinv[e] = rsqrtf(g_deg[e]);
    if (e < EE) {
        int s = edge_val(ei, e);
        int d = edge_val(ei, EE + e);
        g_src[e] = s;
        g_dst[e] = d;
        g_norm[e] = rsqrtf(g_deg[s]) * rsqrtf(g_deg[d]);
    }
}

// exclusive scan of (deg-1) over NN nodes; 1 block, 256 threads, 32 nodes each
__global__ void k_scan() {
    __shared__ int part[256];
    int t = threadIdx.x;
    int base = t * 32;
    int cnt[32];
    int s = 0;
#pragma unroll
    for (int i = 0; i < 32; i++) {
        cnt[i] = (int)g_deg[base + i] - 1;
        s += cnt[i];
    }
    part[t] = s;
    __syncthreads();
    for (int off = 1; off < 256; off <<= 1) {
        int v = (t >= off) ? part[t - off] : 0;
        __syncthreads();
        part[t] += v;
        __syncthreads();
    }
    int run = (t > 0) ? part[t - 1] : 0;
#pragma unroll
    for (int i = 0; i < 32; i++) {
        g_rowstart[base + i] = run;
        g_cursor[base + i] = 0;
        run += cnt[i];
    }
    if (t == 255) g_rowstart[NN] = run;
}

__global__ void k_place() {
    int e = blockIdx.x * blockDim.x + threadIdx.x;
    if (e >= EE) return;
    int d = g_dst[e];
    int pos = g_rowstart[d] + atomicAdd(&g_cursor[d], 1);
    g_csrc[pos]  = g_src[e];
    g_cnorm[pos] = g_norm[e];
}

// ---------------- CSR gather aggregation ----------------
// layer 1: out[r,:] = dinv^2 * x[r,:] + sum norm * x[src,:]   -> fp16 out
// 2 rows per block: 256 threads = 2 x 128 float4 lanes
__global__ void k_gather1(const float* __restrict__ x, __half* __restrict__ out) {
    const int r = blockIdx.x * 2 + (threadIdx.x >> 7);
    const int f = threadIdx.x & 127;       // 0..127 (float4 lanes, F=512)
    const int s0 = g_rowstart[r], s1 = g_rowstart[r + 1];
    float di = g_dinv[r];
    float self = di * di;
    float4 v = ((const float4*)x)[(size_t)r * 128 + f];
    float4 acc = make_float4(v.x * self, v.y * self, v.z * self, v.w * self);
    for (int i = s0; i < s1; i++) {
        int src = g_csrc[i];
        float nrm = g_cnorm[i];
        float4 u = ((const float4*)x)[(size_t)src * 128 + f];
        acc.x += nrm * u.x; acc.y += nrm * u.y;
        acc.z += nrm * u.z; acc.w += nrm * u.w;
    }
    __half2 h0 = __floats2half2_rn(acc.x, acc.y);
    __half2 h1 = __floats2half2_rn(acc.z, acc.w);
    uint2 p;
    p.x = *(uint32_t*)&h0;
    p.y = *(uint32_t*)&h1;
    ((uint2*)out)[(size_t)r * 128 + f] = p;
}

// layer 2 (fp16 in/out): out[r,:] = relu( dinv^2*t2[r,:] + sum norm*t2[src,:] + bias )
__global__ void k_gather2h(const __half* __restrict__ t2, const float* __restrict__ bias,
                           __half* __restrict__ out) {
    const int r = blockIdx.x;
    const int f = threadIdx.x;             // 0..255 (4-half lanes, F=1024)
    const int s0 = g_rowstart[r], s1 = g_rowstart[r + 1];
    float di = g_dinv[r];
    float self = di * di;
    uint2 v = ((const uint2*)t2)[(size_t)r * 256 + f];
    float2 f0 = __half22float2(*(__half2*)&v.x);
    float2 f1 = __half22float2(*(__half2*)&v.y);
    float4 acc = make_float4(f0.x * self, f0.y * self, f1.x * self, f1.y * self);
    for (int i = s0; i < s1; i++) {
        int src = g_csrc[i];
        float nrm = g_cnorm[i];
        uint2 u = ((const uint2*)t2)[(size_t)src * 256 + f];
        float2 u0 = __half22float2(*(__half2*)&u.x);
        float2 u1 = __half22float2(*(__half2*)&u.y);
        acc.x += nrm * u0.x; acc.y += nrm * u0.y;
        acc.z += nrm * u1.x; acc.w += nrm * u1.y;
    }
    float4 b = ((const float4*)bias)[f];
    acc.x = fmaxf(acc.x + b.x, 0.0f);
    acc.y = fmaxf(acc.y + b.y, 0.0f);
    acc.z = fmaxf(acc.z + b.z, 0.0f);
    acc.w = fmaxf(acc.w + b.w, 0.0f);
    __half2 o0 = __floats2half2_rn(acc.x, acc.y);
    __half2 o1 = __floats2half2_rn(acc.z, acc.w);
    uint2 p;
    p.x = *(uint32_t*)&o0;
    p.y = *(uint32_t*)&o1;
    ((uint2*)out)[(size_t)r * 256 + f] = p;
}

// layer 3 fused: gather (F=10) + bias + log_softmax, 16 rows per block (160 thr)
__global__ void k_g3_lsm(const float* __restrict__ t3, const float* __restrict__ b3,
                         float* __restrict__ out) {
    __shared__ float sv[16][F_OUT];
    __shared__ float slse[16];
    const int ty = threadIdx.x / F_OUT;    // 0..15
    const int f  = threadIdx.x % F_OUT;    // 0..9
    const int r  = blockIdx.x * 16 + ty;
    const int s0 = g_rowstart[r], s1 = g_rowstart[r + 1];
    float di = g_dinv[r];
    float acc = di * di * t3[(size_t)r * F_OUT + f];
    for (int i = s0; i < s1; i++)
        acc += g_cnorm[i] * t3[(size_t)g_csrc[i] * F_OUT + f];
    acc += b3[f];
    sv[ty][f] = acc;
    __syncthreads();
    if (f == 0) {
        float mx = -1e30f;
#pragma unroll
        for (int n = 0; n < F_OUT; n++) mx = fmaxf(mx, sv[ty][n]);
        float s = 0.0f;
#pragma unroll
        for (int n = 0; n < F_OUT; n++) s += expf(sv[ty][n] - mx);
        slse[ty] = mx + logf(s);
    }
    __syncthreads();
    out[(size_t)r * F_OUT + f] = acc - slse[ty];
}

// ---------------- transpose + convert: in[R][C] fp32 -> out[C][R] fp16 ----------------
__global__ void k_transpose_h(const float* __restrict__ in, __half* __restrict__ out,
                              int R, int C) {
    __shared__ float t[32][33];
    int c0 = blockIdx.x * 32, r0 = blockIdx.y * 32;
#pragma unroll
    for (int i = threadIdx.y; i < 32; i += 8)
        t[i][threadIdx.x] = in[(size_t)(r0 + i) * C + c0 + threadIdx.x];
    __syncthreads();
#pragma unroll
    for (int i = threadIdx.y; i < 32; i += 8)
        out[(size_t)(c0 + i) * R + r0 + threadIdx.x] = __float2half(t[threadIdx.x][i]);
}

// ---------------- FP16 tensor-core GEMM, cp.async 3-stage pipeline ----------------
// (Exact R8 known-good configuration: 128x128, 256 thr, 2 CTA/SM, scalar LDS.)
// C[M,N] = A[M,K] @ B[N,K]^T : A, B fp16 k-contiguous.

#define HLD 40                         // halves per smem row (32 + 8 pad)
#define HSTAGE (128 * HLD)             // halves per operand per stage (5120)
#define NSTAGE 3
#define GEMM_SMEM (NSTAGE * HSTAGE * 2 * 2)   // 61440 bytes

__device__ __forceinline__ uint32_t smem_u32(const void* p) {
    uint32_t a;
    asm("{ .reg .u64 t; cvta.to.shared.u64 t, %1; cvt.u32.u64 %0, t; }" : "=r"(a) : "l"(p));
    return a;
}

__device__ __forceinline__ void mma_f16(float c[4], uint32_t a0, uint32_t a1,
                                        uint32_t a2, uint32_t a3,
                                        uint32_t b0, uint32_t b1) {
    asm volatile(
        "mma.sync.aligned.m16n8k16.row.col.f32.f16.f16.f32 "
        "{%0,%1,%2,%3}, {%4,%5,%6,%7}, {%8,%9}, {%0,%1,%2,%3};"
        : "+f"(c[0]), "+f"(c[1]), "+f"(c[2]), "+f"(c[3])
        : "r"(a0), "r"(a1), "r"(a2), "r"(a3), "r"(b0), "r"(b1));
}

template<bool BIAS_RELU, bool OUT_HALF>
__global__ __launch_bounds__(256, 2)
void hgemm(const __half* __restrict__ A, const __half* __restrict__ B,
           const float* __restrict__ bias, void* __restrict__ Cv,
           int M, int N, int K) {
    extern __shared__ __half smh[];
    const uint32_t sb = smem_u32(smh);

    const int tid  = threadIdx.x;
    const int lane = tid & 31;
    const int w    = tid >> 5;
    const int wm   = w >> 2;
    const int wn   = w & 3;
    const int bm   = blockIdx.y * 128;
    const int bn   = blockIdx.x * 128;

    // chunk mapping for cp.async: 512 16B-chunks per operand; thread does 2 + 2
    const int r0 = tid >> 2;            // rows 0..63 (and +64)
    const int kc = tid & 3;             // 8-half group

    float acc[4][4][4];
#pragma unroll
    for (int i = 0; i < 4; i++)
#pragma unroll
        for (int j = 0; j < 4; j++)
#pragma unroll
            for (int r = 0; r < 4; r++) acc[i][j][r] = 0.0f;

    const int nch = K >> 5;

    // byte offsets: A stage s at s*HSTAGE*2; B at (NSTAGE + s)*HSTAGE*2
    auto issue = [&](int chunk, int s) {
        const __half* Ag = A + (size_t)bm * K + chunk * 32;
        const __half* Bg = B + (size_t)bn * K + chunk * 32;
        const uint32_t Ab = sb + s * (HSTAGE * 2);
        const uint32_t Bb = sb + (NSTAGE + s) * (HSTAGE * 2);
#pragma unroll
        for (int j = 0; j < 2; j++) {
            const int row = r0 + j * 64;
            const uint32_t so = (uint32_t)(row * HLD + kc * 8) * 2;
            const __half* ga = Ag + (size_t)row * K + kc * 8;
            const __half* gb = Bg + (size_t)row * K + kc * 8;
            asm volatile("cp.async.cg.shared.global [%0], [%1], 16;" :: "r"(Ab + so), "l"(ga));
            asm volatile("cp.async.cg.shared.global [%0], [%1], 16;" :: "r"(Bb + so), "l"(gb));
        }
    };

    issue(0, 0);
    asm volatile("cp.async.commit_group;" ::: "memory");
    if (nch > 1) issue(1, 1);
    asm volatile("cp.async.commit_group;" ::: "memory");

    const int g = lane >> 2;
    const int t = lane & 3;

    int st = 0;
    for (int i = 0; i < nch; i++) {
        asm volatile("cp.async.wait_group 1;" ::: "memory");
        __syncthreads();

        const __half* Ac = smh + st * HSTAGE;
        const __half* Bc = smh + (NSTAGE + st) * HSTAGE;
#pragma unroll
        for (int kk = 0; kk < 2; kk++) {
            const int kb = kk * 16 + 2 * t;
            uint32_t af[4][4];
#pragma unroll
            for (int mt = 0; mt < 4; mt++) {
                const int mrow = wm * 64 + mt * 16 + g;
                af[mt][0] = *(const uint32_t*)&Ac[(mrow    ) * HLD + kb    ];
                af[mt][1] = *(const uint32_t*)&Ac[(mrow + 8) * HLD + kb    ];
                af[mt][2] = *(const uint32_t*)&Ac[(mrow    ) * HLD + kb + 8];
                af[mt][3] = *(const uint32_t*)&Ac[(mrow + 8) * HLD + kb + 8];
            }
            uint32_t bf[4][2];
#pragma unroll
            for (int nt = 0; nt < 4; nt++) {
                const int nrow = wn * 32 + nt * 8 + g;
                bf[nt][0] = *(const uint32_t*)&Bc[nrow * HLD + kb    ];
                bf[nt][1] = *(const uint32_t*)&Bc[nrow * HLD + kb + 8];
            }
#pragma unroll
            for (int mt = 0; mt < 4; mt++)
#pragma unroll
                for (int nt = 0; nt < 4; nt++)
                    mma_f16(acc[mt][nt], af[mt][0], af[mt][1], af[mt][2], af[mt][3],
                            bf[nt][0], bf[nt][1]);
        }

        __syncthreads();   // all warps done with stage (st+2)%3's future target
        if (i + 2 < nch) issue(i + 2, (st + 2) % NSTAGE);
        asm volatile("cp.async.commit_group;" ::: "memory");
        st = (st + 1) % NSTAGE;
    }

    // epilogue
    const int c2 = t * 2;
#pragma unroll
    for (int mt = 0; mt < 4; mt++) {
#pragma unroll
        for (int nt = 0; nt < 4; nt++) {
            int row = bm + wm * 64 + mt * 16 + g;
            int col = bn + wn * 32 + nt * 8 + c2;
            float v0 = acc[mt][nt][0], v1 = acc[mt][nt][1];
            float v2 = acc[mt][nt][2], v3 = acc[mt][nt][3];
            if (BIAS_RELU) {
                float bb0 = bias[col], bb1 = bias[col + 1];
                v0 = fmaxf(v0 + bb0, 0.0f); v1 = fmaxf(v1 + bb1, 0.0f);
                v2 = fmaxf(v2 + bb0, 0.0f); v3 = fmaxf(v3 + bb1, 0.0f);
            }
            if (OUT_HALF) {
                __half* C = (__half*)Cv;
                *(__half2*)&C[(size_t)row * N + col]       = __floats2half2_rn(v0, v1);
                *(__half2*)&C[(size_t)(row + 8) * N + col] = __floats2half2_rn(v2, v3);
            } else {
                float* C = (float*)Cv;
                *(float2*)&C[(size_t)row * N + col]       = make_float2(v0, v1);
                *(float2*)&C[(size_t)(row + 8) * N + col] = make_float2(v2, v3);
            }
        }
    }
}

// small GEMM: C[NN,10] = A_h[NN,1024] @ B[1024,10]; W3 staged in smem
__global__ void sgemm_small_h(const __half* __restrict__ A, const float* __restrict__ B,
                              float* __restrict__ C) {
    __shared__ float Ws[H2D * F_OUT];
    int tid = threadIdx.y * F_OUT + threadIdx.x;
    for (int i = tid; i < H2D * F_OUT; i += F_OUT * 16) Ws[i] = B[i];
    __syncthreads();
    int m = blockIdx.x * 16 + threadIdx.y;
    int n = threadIdx.x;
    const uint4* a = (const uint4*)(A + (size_t)m * H2D);
    float s = 0.0f;
#pragma unroll 4
    for (int k8 = 0; k8 < H2D / 8; k8++) {
        uint4 v = a[k8];
        float2 f0 = __half22float2(*(__half2*)&v.x);
        float2 f1 = __half22float2(*(__half2*)&v.y);
        float2 f2 = __half22float2(*(__half2*)&v.z);
        float2 f3 = __half22float2(*(__half2*)&v.w);
        int k = k8 * 8;
        s += f0.x * Ws[(k + 0) * F_OUT + n] + f0.y * Ws[(k + 1) * F_OUT + n];
        s += f1.x * Ws[(k + 2) * F_OUT + n] + f1.y * Ws[(k + 3) * F_OUT + n];
        s += f2.x * Ws[(k + 4) * F_OUT + n] + f2.y * Ws[(k + 5) * F_OUT + n];
        s += f3.x * Ws[(k + 6) * F_OUT + n] + f3.y * Ws[(k + 7) * F_OUT + n];
    }
    C[m * F_OUT + n] = s;
}

// ---------------- launch ----------------
extern "C" void kernel_launch(void* const* d_in, const int* in_sizes, int n_in,
                              void* d_out, int out_size) {
    const float* x  = (const float*)d_in[0];
    const float* W1 = (const float*)d_in[1];
    const float* b1 = (const float*)d_in[2];
    const float* W2 = (const float*)d_in[3];
    const float* b2 = (const float*)d_in[4];
    const float* W3 = (const float*)d_in[5];
    const float* b3 = (const float*)d_in[6];
    const void*  ei = d_in[7];
    float* out = (float*)d_out;

    float *t3;
    __half *aggxh, *w1t, *w2t, *h1h, *t2h, *h2h;
    cudaGetSymbolAddress((void**)&aggxh, g_aggxh);
    cudaGetSymbolAddress((void**)&w1t,   g_w1t);
    cudaGetSymbolAddress((void**)&w2t,   g_w2t);
    cudaGetSymbolAddress((void**)&h1h,   g_h1h);
    cudaGetSymbolAddress((void**)&t2h,   g_t2h);
    cudaGetSymbolAddress((void**)&h2h,   g_h2h);
    cudaGetSymbolAddress((void**)&t3,    g_t3);

    cudaFuncSetAttribute(hgemm<true, true>,  cudaFuncAttributeMaxDynamicSharedMemorySize, GEMM_SMEM);
    cudaFuncSetAttribute(hgemm<false, true>, cudaFuncAttributeMaxDynamicSharedMemorySize, GEMM_SMEM);

    // weight transposes (independent of graph preprocessing)
    {
        dim3 blk(32, 8);
        dim3 g1(H1D / 32, F_IN / 32);
        k_transpose_h<<<g1, blk>>>(W1, w1t, F_IN, H1D);
        dim3 g2(H2D / 32, H1D / 32);
        k_transpose_h<<<g2, blk>>>(W2, w2t, H1D, H2D);
    }

    // graph preprocessing: degrees, norms, CSR by destination
    k_deg_init<<<(NN + 255) / 256, 256>>>(ei);
    k_deg_count<<<(EE + 255) / 256, 256>>>(ei);
    k_prep<<<(EE + 255) / 256, 256>>>(ei);
    k_scan<<<1, 256>>>();
    k_place<<<(EE + 255) / 256, 256>>>();

    // ---- layer 1: CSR gather (fp32 -> fp16), GEMM + fused bias/relu (fp16 out)
    {
        k_gather1<<<NN / 2, 256>>>(x, aggxh);
        dim3 grid(H1D / 128, NN / 128);
        hgemm<true, true><<<grid, 256, GEMM_SMEM>>>(aggxh, w1t, b1, h1h, NN, H1D, F_IN);
    }

    // ---- layer 2: GEMM (4096 -> 1024, fp16 out), CSR gather + fused bias/relu (fp16)
    {
        dim3 grid(H2D / 128, NN / 128);
        hgemm<false, true><<<grid, 256, GEMM_SMEM>>>(h1h, w2t, nullptr, t2h, NN, H2D, H1D);
        k_gather2h<<<NN, 256>>>(t2h, b2, h2h);
    }

    // ---- layer 3: small GEMM (1024 -> 10), fused gather + bias + log_softmax
    {
        dim3 blk(F_OUT, 16);
        sgemm_small_h<<<NN / 16, blk>>>(h2h, W3, t3);
        k_g3_lsm<<<NN / 16, 16 * F_OUT>>>(t3, b3, out);
    }
}

// round 15
// speedup vs baseline: 1.1242x; 1.0063x over previous
#include <cuda_runtime.h>
#include <cuda_fp16.h>
#include <cuda_bf16.h>
#include <math.h>
#include <stdint.h>

// Problem constants (fixed by the dataset)
#define NN 8192
#define EE 65536
#define F_IN 512
#define H1D 4096
#define H2D 1024
#define F_OUT 10

// ---------------- scratch (device globals: allocation-free) ----------------
__device__ int    g_is64;
__device__ float  g_deg[NN];
__device__ float  g_dinv[NN];
__device__ int    g_src[EE];
__device__ int    g_dst[EE];
__device__ float  g_norm[EE];
__device__ int    g_rowstart[NN + 1];
__device__ int    g_cursor[NN];
__device__ int    g_csrc[EE];
__device__ float  g_cnorm[EE];
__device__ __half g_aggxh[(size_t)NN * F_IN];    // fp16 aggregated x
__device__ __half g_w1t[(size_t)H1D * F_IN];     // W1^T fp16 [4096][512]
__device__ __half g_w2t[(size_t)H2D * H1D];      // W2^T fp16 [1024][4096]
__device__ __half g_h1h[(size_t)NN * H1D];       // layer1 out fp16
__device__ __half g_t2h[(size_t)NN * H2D];       // h1 @ W2 fp16
__device__ __half g_h2h[(size_t)NN * H2D];       // relu(A t2 + b2) fp16
__device__ float  g_t3[(size_t)NN * F_OUT];

// ---------------- graph preprocessing ----------------
__device__ __forceinline__ int edge_val(const void* ei, int idx) {
    if (g_is64) return (int)((const long long*)ei)[idx];
    return ((const int*)ei)[idx];
}

// deg init + dtype probe in one kernel (probe in block 0, thread 0)
__global__ void k_deg_init(const void* __restrict__ ei) {
    int i = blockIdx.x * blockDim.x + threadIdx.x;
    if (i < NN) g_deg[i] = 1.0f;
    if (i == 0) {
        const long long* p = (const long long*)ei;
        int ok64 = 1;
        for (int j = 0; j < 64; j++) {
            long long v = p[j];
            if (v < 0 || v >= NN) { ok64 = 0; break; }
        }
        g_is64 = ok64;
    }
}

__global__ void k_deg_count(const void* __restrict__ ei) {
    int e = blockIdx.x * blockDim.x + threadIdx.x;
    if (e < EE) atomicAdd(&g_deg[edge_val(ei, EE + e)], 1.0f);
}

// fused: dinv (i < NN) + edge src/dst/norm (e < EE); both depend only on g_deg
__global__ void k_prep(const void* __restrict__ ei) {
    int e = blockIdx.x * blockDim.x + threadIdx.x;
    if (e < NN) g_dinv[e] = rsqrtf(g_deg[e]);
    if (e < EE) {
        int s = edge_val(ei, e);
        int d = edge_val(ei, EE + e);
        g_src[e] = s;
        g_dst[e] = d;
        g_norm[e] = rsqrtf(g_deg[s]) * rsqrtf(g_deg[d]);
    }
}

// exclusive scan of (deg-1) over NN nodes; 1 block, 256 threads, 32 nodes each
__global__ void k_scan() {
    __shared__ int part[256];
    int t = threadIdx.x;
    int base = t * 32;
    int cnt[32];
    int s = 0;
#pragma unroll
    for (int i = 0; i < 32; i++) {
        cnt[i] = (int)g_deg[base + i] - 1;
        s += cnt[i];
    }
    part[t] = s;
    __syncthreads();
    for (int off = 1; off < 256; off <<= 1) {
        int v = (t >= off) ? part[t - off] : 0;
        __syncthreads();
        part[t] += v;
        __syncthreads();
    }
    int run = (t > 0) ? part[t - 1] : 0;
#pragma unroll
    for (int i = 0; i < 32; i++) {
        g_rowstart[base + i] = run;
        g_cursor[base + i] = 0;
        run += cnt[i];
    }
    if (t == 255) g_rowstart[NN] = run;
}

__global__ void k_place() {
    int e = blockIdx.x * blockDim.x + threadIdx.x;
    if (e >= EE) return;
    int d = g_dst[e];
    int pos = g_rowstart[d] + atomicAdd(&g_cursor[d], 1);
    g_csrc[pos]  = g_src[e];
    g_cnorm[pos] = g_norm[e];
}

// ---------------- CSR gather aggregation ----------------
// layer 1: out[r,:] = dinv^2 * x[r,:] + sum norm * x[src,:]   -> fp16 out
// 2 rows per block: 256 threads = 2 x 128 float4 lanes
__global__ void k_gather1(const float* __restrict__ x, __half* __restrict__ out) {
    const int r = blockIdx.x * 2 + (threadIdx.x >> 7);
    const int f = threadIdx.x & 127;       // 0..127 (float4 lanes, F=512)
    const int s0 = g_rowstart[r], s1 = g_rowstart[r + 1];
    float di = g_dinv[r];
    float self = di * di;
    float4 v = ((const float4*)x)[(size_t)r * 128 + f];
    float4 acc = make_float4(v.x * self, v.y * self, v.z * self, v.w * self);
    for (int i = s0; i < s1; i++) {
        int src = g_csrc[i];
        float nrm = g_cnorm[i];
        float4 u = ((const float4*)x)[(size_t)src * 128 + f];
        acc.x += nrm * u.x; acc.y += nrm * u.y;
        acc.z += nrm * u.z; acc.w += nrm * u.w;
    }
    __half2 h0 = __floats2half2_rn(acc.x, acc.y);
    __half2 h1 = __floats2half2_rn(acc.z, acc.w);
    uint2 p;
    p.x = *(uint32_t*)&h0;
    p.y = *(uint32_t*)&h1;
    ((uint2*)out)[(size_t)r * 128 + f] = p;
}

// layer 2 (fp16 in/out): out[r,:] = relu( dinv^2*t2[r,:] + sum norm*t2[src,:] + bias )
__global__ void k_gather2h(const __half* __restrict__ t2, const float* __restrict__ bias,
                           __half* __restrict__ out) {
    const int r = blockIdx.x;
    const int f = threadIdx.x;             // 0..255 (4-half lanes, F=1024)
    const int s0 = g_rowstart[r], s1 = g_rowstart[r + 1];
    float di = g_dinv[r];
    float self = di * di;
    uint2 v = ((const uint2*)t2)[(size_t)r * 256 + f];
    float2 f0 = __half22float2(*(__half2*)&v.x);
    float2 f1 = __half22float2(*(__half2*)&v.y);
    float4 acc = make_float4(f0.x * self, f0.y * self, f1.x * self, f1.y * self);
    for (int i = s0; i < s1; i++) {
        int src = g_csrc[i];
        float nrm = g_cnorm[i];
        uint2 u = ((const uint2*)t2)[(size_t)src * 256 + f];
        float2 u0 = __half22float2(*(__half2*)&u.x);
        float2 u1 = __half22float2(*(__half2*)&u.y);
        acc.x += nrm * u0.x; acc.y += nrm * u0.y;
        acc.z += nrm * u1.x; acc.w += nrm * u1.y;
    }
    float4 b = ((const float4*)bias)[f];
    acc.x = fmaxf(acc.x + b.x, 0.0f);
    acc.y = fmaxf(acc.y + b.y, 0.0f);
    acc.z = fmaxf(acc.z + b.z, 0.0f);
    acc.w = fmaxf(acc.w + b.w, 0.0f);
    __half2 o0 = __floats2half2_rn(acc.x, acc.y);
    __half2 o1 = __floats2half2_rn(acc.z, acc.w);
    uint2 p;
    p.x = *(uint32_t*)&o0;
    p.y = *(uint32_t*)&o1;
    ((uint2*)out)[(size_t)r * 256 + f] = p;
}

// layer 3 fused: gather (F=10) + bias + log_softmax, 16 rows per block (160 thr)
__global__ void k_g3_lsm(const float* __restrict__ t3, const float* __restrict__ b3,
                         float* __restrict__ out) {
    __shared__ float sv[16][F_OUT];
    __shared__ float slse[16];
    const int ty = threadIdx.x / F_OUT;    // 0..15
    const int f  = threadIdx.x % F_OUT;    // 0..9
    const int r  = blockIdx.x * 16 + ty;
    const int s0 = g_rowstart[r], s1 = g_rowstart[r + 1];
    float di = g_dinv[r];
    float acc = di * di * t3[(size_t)r * F_OUT + f];
    for (int i = s0; i < s1; i++)
        acc += g_cnorm[i] * t3[(size_t)g_csrc[i] * F_OUT + f];
    acc += b3[f];
    sv[ty][f] = acc;
    __syncthreads();
    if (f == 0) {
        float mx = -1e30f;
#pragma unroll
        for (int n = 0; n < F_OUT; n++) mx = fmaxf(mx, sv[ty][n]);
        float s = 0.0f;
#pragma unroll
        for (int n = 0; n < F_OUT; n++) s += expf(sv[ty][n] - mx);
        slse[ty] = mx + logf(s);
    }
    __syncthreads();
    out[(size_t)r * F_OUT + f] = acc - slse[ty];
}

// ---------------- transpose + convert: in[R][C] fp32 -> out[C][R] fp16 ----------------
__global__ void k_transpose_h(const float* __restrict__ in, __half* __restrict__ out,
                              int R, int C) {
    __shared__ float t[32][33];
    int c0 = blockIdx.x * 32, r0 = blockIdx.y * 32;
#pragma unroll
    for (int i = threadIdx.y; i < 32; i += 8)
        t[i][threadIdx.x] = in[(size_t)(r0 + i) * C + c0 + threadIdx.x];
    __syncthreads();
#pragma unroll
    for (int i = threadIdx.y; i < 32; i += 8)
        out[(size_t)(c0 + i) * R + r0 + threadIdx.x] = __float2half(t[threadIdx.x][i]);
}

// ---------------- FP16 tensor-core GEMM, cp.async 3-stage pipeline ----------------
// (Exact R8 known-good configuration: 128x128, 256 thr, 2 CTA/SM, scalar LDS.)
// C[M,N] = A[M,K] @ B[N,K]^T : A, B fp16 k-contiguous.

#define HLD 40                         // halves per smem row (32 + 8 pad)
#define HSTAGE (128 * HLD)             // halves per operand per stage (5120)
#define NSTAGE 3
#define GEMM_SMEM (NSTAGE * HSTAGE * 2 * 2)   // 61440 bytes

__device__ __forceinline__ uint32_t smem_u32(const void* p) {
    uint32_t a;
    asm("{ .reg .u64 t; cvta.to.shared.u64 t, %1; cvt.u32.u64 %0, t; }" : "=r"(a) : "l"(p));
    return a;
}

__device__ __forceinline__ void mma_f16(float c[4], uint32_t a0, uint32_t a1,
                                        uint32_t a2, uint32_t a3,
                                        uint32_t b0, uint32_t b1) {
    asm volatile(
        "mma.sync.aligned.m16n8k16.row.col.f32.f16.f16.f32 "
        "{%0,%1,%2,%3}, {%4,%5,%6,%7}, {%8,%9}, {%0,%1,%2,%3};"
        : "+f"(c[0]), "+f"(c[1]), "+f"(c[2]), "+f"(c[3])
        : "r"(a0), "r"(a1), "r"(a2), "r"(a3), "r"(b0), "r"(b1));
}

template<bool BIAS_RELU, bool OUT_HALF>
__global__ __launch_bounds__(256, 2)
void hgemm(const __half* __restrict__ A, const __half* __restrict__ B,
           const float* __restrict__ bias, void* __restrict__ Cv,
           int M, int N, int K) {
    extern __shared__ __half smh[];
    const uint32_t sb = smem_u32(smh);

    const int tid  = threadIdx.x;
    const int lane = tid & 31;
    const int w    = tid >> 5;
    const int wm   = w >> 2;
    const int wn   = w & 3;
    const int bm   = blockIdx.y * 128;
    const int bn   = blockIdx.x * 128;

    // chunk mapping for cp.async: 512 16B-chunks per operand; thread does 2 + 2
    const int r0 = tid >> 2;            // rows 0..63 (and +64)
    const int kc = tid & 3;             // 8-half group

    float acc[4][4][4];
#pragma unroll
    for (int i = 0; i < 4; i++)
#pragma unroll
        for (int j = 0; j < 4; j++)
#pragma unroll
            for (int r = 0; r < 4; r++) acc[i][j][r] = 0.0f;

    const int nch = K >> 5;

    // byte offsets: A stage s at s*HSTAGE*2; B at (NSTAGE + s)*HSTAGE*2
    auto issue = [&](int chunk, int s) {
        const __half* Ag = A + (size_t)bm * K + chunk * 32;
        const __half* Bg = B + (size_t)bn * K + chunk * 32;
        const uint32_t Ab = sb + s * (HSTAGE * 2);
        const uint32_t Bb = sb + (NSTAGE + s) * (HSTAGE * 2);
#pragma unroll
        for (int j = 0; j < 2; j++) {
            const int row = r0 + j * 64;
            const uint32_t so = (uint32_t)(row * HLD + kc * 8) * 2;
            const __half* ga = Ag + (size_t)row * K + kc * 8;
            const __half* gb = Bg + (size_t)row * K + kc * 8;
            asm volatile("cp.async.cg.shared.global [%0], [%1], 16;" :: "r"(Ab + so), "l"(ga));
            asm volatile("cp.async.cg.shared.global [%0], [%1], 16;" :: "r"(Bb + so), "l"(gb));
        }
    };

    issue(0, 0);
    asm volatile("cp.async.commit_group;" ::: "memory");
    if (nch > 1) issue(1, 1);
    asm volatile("cp.async.commit_group;" ::: "memory");

    const int g = lane >> 2;
    const int t = lane & 3;

    int st = 0;
    for (int i = 0; i < nch; i++) {
        asm volatile("cp.async.wait_group 1;" ::: "memory");
        __syncthreads();

        const __half* Ac = smh + st * HSTAGE;
        const __half* Bc = smh + (NSTAGE + st) * HSTAGE;
#pragma unroll
        for (int kk = 0; kk < 2; kk++) {
            const int kb = kk * 16 + 2 * t;
            uint32_t af[4][4];
#pragma unroll
            for (int mt = 0; mt < 4; mt++) {
                const int mrow = wm * 64 + mt * 16 + g;
                af[mt][0] = *(const uint32_t*)&Ac[(mrow    ) * HLD + kb    ];
                af[mt][1] = *(const uint32_t*)&Ac[(mrow + 8) * HLD + kb    ];
                af[mt][2] = *(const uint32_t*)&Ac[(mrow    ) * HLD + kb + 8];
                af[mt][3] = *(const uint32_t*)&Ac[(mrow + 8) * HLD + kb + 8];
            }
            uint32_t bf[4][2];
#pragma unroll
            for (int nt = 0; nt < 4; nt++) {
                const int nrow = wn * 32 + nt * 8 + g;
                bf[nt][0] = *(const uint32_t*)&Bc[nrow * HLD + kb    ];
                bf[nt][1] = *(const uint32_t*)&Bc[nrow * HLD + kb + 8];
            }
#pragma unroll
            for (int mt = 0; mt < 4; mt++)
#pragma unroll
                for (int nt = 0; nt < 4; nt++)
                    mma_f16(acc[mt][nt], af[mt][0], af[mt][1], af[mt][2], af[mt][3],
                            bf[nt][0], bf[nt][1]);
        }

        __syncthreads();   // all warps done with stage (st+2)%3's future target
        if (i + 2 < nch) issue(i + 2, (st + 2) % NSTAGE);
        asm volatile("cp.async.commit_group;" ::: "memory");
        st = (st + 1) % NSTAGE;
    }

    // epilogue
    const int c2 = t * 2;
#pragma unroll
    for (int mt = 0; mt < 4; mt++) {
#pragma unroll
        for (int nt = 0; nt < 4; nt++) {
            int row = bm + wm * 64 + mt * 16 + g;
            int col = bn + wn * 32 + nt * 8 + c2;
            float v0 = acc[mt][nt][0], v1 = acc[mt][nt][1];
            float v2 = acc[mt][nt][2], v3 = acc[mt][nt][3];
            if (BIAS_RELU) {
                float bb0 = bias[col], bb1 = bias[col + 1];
                v0 = fmaxf(v0 + bb0, 0.0f); v1 = fmaxf(v1 + bb1, 0.0f);
                v2 = fmaxf(v2 + bb0, 0.0f); v3 = fmaxf(v3 + bb1, 0.0f);
            }
            if (OUT_HALF) {
                __half* C = (__half*)Cv;
                *(__half2*)&C[(size_t)row * N + col]       = __floats2half2_rn(v0, v1);
                *(__half2*)&C[(size_t)(row + 8) * N + col] = __floats2half2_rn(v2, v3);
            } else {
                float* C = (float*)Cv;
                *(float2*)&C[(size_t)row * N + col]       = make_float2(v0, v1);
                *(float2*)&C[(size_t)(row + 8) * N + col] = make_float2(v2, v3);
            }
        }
    }
}

// small GEMM: C[NN,10] = A_h[NN,1024] @ B[1024,10]; W3 staged in smem
__global__ void sgemm_small_h(const __half* __restrict__ A, const float* __restrict__ B,
                              float* __restrict__ C) {
    __shared__ float Ws[H2D * F_OUT];
    int tid = threadIdx.y * F_OUT + threadIdx.x;
    for (int i = tid; i < H2D * F_OUT; i += F_OUT * 16) Ws[i] = B[i];
    __syncthreads();
    int m = blockIdx.x * 16 + threadIdx.y;
    int n = threadIdx.x;
    const uint4* a = (const uint4*)(A + (size_t)m * H2D);
    float s = 0.0f;
#pragma unroll 4
    for (int k8 = 0; k8 < H2D / 8; k8++) {
        uint4 v = a[k8];
        float2 f0 = __half22float2(*(__half2*)&v.x);
        float2 f1 = __half22float2(*(__half2*)&v.y);
        float2 f2 = __half22float2(*(__half2*)&v.z);
        float2 f3 = __half22float2(*(__half2*)&v.w);
        int k = k8 * 8;
        s += f0.x * Ws[(k + 0) * F_OUT + n] + f0.y * Ws[(k + 1) * F_OUT + n];
        s += f1.x * Ws[(k + 2) * F_OUT + n] + f1.y * Ws[(k + 3) * F_OUT + n];
        s += f2.x * Ws[(k + 4) * F_OUT + n] + f2.y * Ws[(k + 5) * F_OUT + n];
        s += f3.x * Ws[(k + 6) * F_OUT + n] + f3.y * Ws[(k + 7) * F_OUT + n];
    }
    C[m * F_OUT + n] = s;
}

// ---------------- launch ----------------
extern "C" void kernel_launch(void* const* d_in, const int* in_sizes, int n_in,
                              void* d_out, int out_size) {
    const float* x  = (const float*)d_in[0];
    const float* W1 = (const float*)d_in[1];
    const float* b1 = (const float*)d_in[2];
    const float* W2 = (const float*)d_in[3];
    const float* b2 = (const float*)d_in[4];
    const float* W3 = (const float*)d_in[5];
    const float* b3 = (const float*)d_in[6];
    const void*  ei = d_in[7];
    float* out = (float*)d_out;

    float *t3;
    __half *aggxh, *w1t, *w2t, *h1h, *t2h, *h2h;
    cudaGetSymbolAddress((void**)&aggxh, g_aggxh);
    cudaGetSymbolAddress((void**)&w1t,   g_w1t);
    cudaGetSymbolAddress((void**)&w2t,   g_w2t);
    cudaGetSymbolAddress((void**)&h1h,   g_h1h);
    cudaGetSymbolAddress((void**)&t2h,   g_t2h);
    cudaGetSymbolAddress((void**)&h2h,   g_h2h);
    cudaGetSymbolAddress((void**)&t3,    g_t3);

    cudaFuncSetAttribute(hgemm<true, true>,  cudaFuncAttributeMaxDynamicSharedMemorySize, GEMM_SMEM);
    cudaFuncSetAttribute(hgemm<false, true>, cudaFuncAttributeMaxDynamicSharedMemorySize, GEMM_SMEM);

    // Fork a side stream for the weight transposes so they run concurrently
    // with graph preprocessing + gather1 in the captured graph. Host-side
    // stream/event creation happens at capture time only (replays are free).
    cudaStream_t s1;
    cudaEvent_t evFork, evW1, evW2;
    cudaStreamCreateWithFlags(&s1, cudaStreamNonBlocking);
    cudaEventCreateWithFlags(&evFork, cudaEventDisableTiming);
    cudaEventCreateWithFlags(&evW1,   cudaEventDisableTiming);
    cudaEventCreateWithFlags(&evW2,   cudaEventDisableTiming);

    // fork point on the main (capture) stream
    cudaEventRecord(evFork, 0);
    cudaStreamWaitEvent(s1, evFork, 0);

    // side stream: weight transposes
    {
        dim3 blk(32, 8);
        dim3 g1(H1D / 32, F_IN / 32);
        k_transpose_h<<<g1, blk, 0, s1>>>(W1, w1t, F_IN, H1D);
        cudaEventRecord(evW1, s1);
        dim3 g2(H2D / 32, H1D / 32);
        k_transpose_h<<<g2, blk, 0, s1>>>(W2, w2t, H1D, H2D);
        cudaEventRecord(evW2, s1);
    }

    // main stream: graph preprocessing (degrees, norms, CSR by destination)
    k_deg_init<<<(NN + 255) / 256, 256>>>(ei);
    k_deg_count<<<(EE + 255) / 256, 256>>>(ei);
    k_prep<<<(EE + 255) / 256, 256>>>(ei);
    k_scan<<<1, 256>>>();
    k_place<<<(EE + 255) / 256, 256>>>();

    // ---- layer 1: CSR gather (fp32 -> fp16), GEMM + fused bias/relu (fp16 out)
    {
        k_gather1<<<NN / 2, 256>>>(x, aggxh);
        cudaStreamWaitEvent(0, evW1, 0);    // join: GEMM1 needs w1t
        dim3 grid(H1D / 128, NN / 128);
        hgemm<true, true><<<grid, 256, GEMM_SMEM>>>(aggxh, w1t, b1, h1h, NN, H1D, F_IN);
    }

    // ---- layer 2: GEMM (4096 -> 1024, fp16 out), CSR gather + fused bias/relu (fp16)
    {
        cudaStreamWaitEvent(0, evW2, 0);    // join: GEMM2 needs w2t
        dim3 grid(H2D / 128, NN / 128);
        hgemm<false, true><<<grid, 256, GEMM_SMEM>>>(h1h, w2t, nullptr, t2h, NN, H2D, H1D);
        k_gather2h<<<NN, 256>>>(t2h, b2, h2h);
    }

    // ---- layer 3: small GEMM (1024 -> 10), fused gather + bias + log_softmax
    {
        dim3 blk(F_OUT, 16);
        sgemm_small_h<<<NN / 16, blk>>>(h2h, W3, t3);
        k_g3_lsm<<<NN / 16, 16 * F_OUT>>>(t3, b3, out);
    }
    // note: streams/events intentionally not destroyed here — the capture
    // referencing them is still open when kernel_launch returns; they are
    // host-side objects only (no device memory), leaked a handful of times.
}